// round 2
// baseline (speedup 1.0000x reference)
#include <cuda_runtime.h>
#include <math.h>

// Problem constants
#define Bc 2
#define Nc 32768
#define Kc 16
#define Dc 256
#define Ac 64
#define Vc 64
#define Hc 512

#define R1 16   // rows per block for row-tiled GEMM kernels
#define TN 4    // points per block in attention kernel

// -------- scratch (device globals; no cudaMalloc allowed) --------
__device__ float g_q[(size_t)Bc * Nc * Ac];
__device__ float g_k[(size_t)Bc * Nc * Ac];
__device__ float g_v[(size_t)Bc * Nc * Vc];
__device__ float g_ctx[(size_t)Bc * Nc * Vc];
__device__ float g_x1[(size_t)Bc * Nc * Dc];
__device__ float g_h2[(size_t)Bc * Nc * Dc];

// ============================================================
// Kernel 1: LN1 + QKV projections.  grid = B*N/R1, 256 threads
// ============================================================
__global__ void k_ln1_qkv(const float* __restrict__ x,
                          const float* __restrict__ g1, const float* __restrict__ b1,
                          const float* __restrict__ Wq, const float* __restrict__ bq,
                          const float* __restrict__ Wk, const float* __restrict__ bk,
                          const float* __restrict__ Wv, const float* __restrict__ bv) {
    __shared__ float hs[R1][Dc];
    const int row0 = blockIdx.x * R1;
    const int tid = threadIdx.x, lane = tid & 31, w = tid >> 5;

    for (int i = tid; i < R1 * Dc; i += 256)
        hs[i >> 8][i & 255] = x[(size_t)row0 * Dc + i];
    __syncthreads();

    // LayerNorm: warp w handles rows 2w, 2w+1
    #pragma unroll
    for (int rr = 0; rr < 2; rr++) {
        int r = w * 2 + rr;
        float s = 0.f;
        #pragma unroll
        for (int i = 0; i < Dc / 32; i++) s += hs[r][lane + 32 * i];
        #pragma unroll
        for (int o = 16; o; o >>= 1) s += __shfl_xor_sync(~0u, s, o);
        float m = s * (1.0f / Dc);
        float v = 0.f;
        #pragma unroll
        for (int i = 0; i < Dc / 32; i++) { float d = hs[r][lane + 32 * i] - m; v += d * d; }
        #pragma unroll
        for (int o = 16; o; o >>= 1) v += __shfl_xor_sync(~0u, v, o);
        float rstd = rsqrtf(v * (1.0f / Dc) + 1e-5f);
        #pragma unroll
        for (int i = 0; i < Dc / 32; i++) {
            int d = lane + 32 * i;
            hs[r][d] = (hs[r][d] - m) * rstd * g1[d] + b1[d];
        }
    }
    __syncthreads();

    if (tid < 192) {
        const float* W; const float* bb; float* out; int col;
        if (tid < 64)       { W = Wq; bb = bq; out = g_q; col = tid; }
        else if (tid < 128) { W = Wk; bb = bk; out = g_k; col = tid - 64; }
        else                { W = Wv; bb = bv; out = g_v; col = tid - 128; }
        float acc[R1];
        #pragma unroll
        for (int r = 0; r < R1; r++) acc[r] = 0.f;
        #pragma unroll 4
        for (int d = 0; d < Dc; d++) {
            float wv = W[d * 64 + col];
            #pragma unroll
            for (int r = 0; r < R1; r++) acc[r] += hs[r][d] * wv;
        }
        float bias = bb[col];
        #pragma unroll
        for (int r = 0; r < R1; r++)
            out[(size_t)(row0 + r) * 64 + col] = acc[r] + bias;
    }
}

// ============================================================
// Kernel 2: attention (ra/rv recompute + scores + softmax + ctx)
// grid = N/TN, 256 threads (8 warps), dynamic smem ~88KB
// ============================================================
__global__ void k_attn(const int* __restrict__ knn_idx,
                       const float* __restrict__ rel,
                       const float* __restrict__ Wpa1, const float* __restrict__ bpa1,
                       const float* __restrict__ Wpa2, const float* __restrict__ bpa2,
                       const float* __restrict__ Wpv1, const float* __restrict__ bpv1,
                       const float* __restrict__ Wpv2, const float* __restrict__ bpv2,
                       const float* __restrict__ Ws1,  const float* __restrict__ bs1,
                       const float* __restrict__ Ws2,  const float* __restrict__ bs2) {
    extern __shared__ float sm[];
    float* wPa1 = sm;              // 192
    float* bPa1 = wPa1 + 192;      // 64
    float* wPa2 = bPa1 + 64;       // 4096
    float* bPa2 = wPa2 + 4096;     // 64
    float* wPv1 = bPa2 + 64;       // 192
    float* bPv1 = wPv1 + 192;      // 64
    float* wPv2 = bPv1 + 64;       // 4096
    float* bPv2 = wPv2 + 4096;     // 64
    float* wS1s = bPv2 + 64;       // 4096
    float* bS1s = wS1s + 4096;     // 64
    float* wS2s = bS1s + 64;       // 64
    float* qs   = wS2s + 64;       // 2*TN*64 = 512
    float* ra_s = qs + 512;        // TN*16*64 = 4096
    float* rv_s = ra_s + 4096;     // 4096
    float* tsc  = rv_s + 4096;     // 8*64 = 512
    float* sc_s = tsc + 512;       // 2*TN*16 = 128
    int*   idx_s = (int*)(sc_s + 128); // TN*16 = 64

    const int tid = threadIdx.x, lane = tid & 31, w = tid >> 5;
    const int nbase = blockIdx.x * TN;

    // cooperative weight loads
    for (int i = tid; i < 192;  i += 256) { wPa1[i] = Wpa1[i]; wPv1[i] = Wpv1[i]; }
    for (int i = tid; i < 64;   i += 256) {
        bPa1[i] = bpa1[i]; bPa2[i] = bpa2[i];
        bPv1[i] = bpv1[i]; bPv2[i] = bpv2[i];
        bS1s[i] = bs1[i];  wS2s[i] = Ws2[i];
    }
    for (int i = tid; i < 4096; i += 256) { wPa2[i] = Wpa2[i]; wPv2[i] = Wpv2[i]; wS1s[i] = Ws1[i]; }
    for (int i = tid; i < 2 * TN * 64; i += 256) {
        int b = i >> 8, nl = (i >> 6) & (TN - 1), a = i & 63;
        qs[i] = g_q[((size_t)b * Nc + nbase + nl) * 64 + a];
    }
    for (int i = tid; i < TN * 16; i += 256)
        idx_s[i] = knn_idx[(size_t)(nbase + (i >> 4)) * Kc + (i & 15)];
    const float bS2v = bs2[0];
    __syncthreads();

    // ---- Stage A: ra/rv (once per (n,k), shared across batches) ----
    for (int it = w; it < TN * Kc; it += 8) {
        int nl = it >> 4, kk = it & 15;
        const float* rp = rel + ((size_t)(nbase + nl) * Kc + kk) * 3;
        float r0 = rp[0], r1 = rp[1], r2 = rp[2];
        float* ts = tsc + w * 64;
        #pragma unroll
        for (int pp = 0; pp < 2; pp++) {
            const float* W1 = pp ? wPv1 : wPa1;
            const float* B1 = pp ? bPv1 : bPa1;
            const float* W2 = pp ? wPv2 : wPa2;
            const float* B2 = pp ? bPv2 : bPa2;
            float* dst = (pp ? rv_s : ra_s) + (nl * Kc + kk) * 64;
            int j0 = lane, j1 = lane + 32;
            float h0 = fmaxf(0.f, fmaf(r2, W1[128 + j0], fmaf(r1, W1[64 + j0], fmaf(r0, W1[j0], B1[j0]))));
            float h1 = fmaxf(0.f, fmaf(r2, W1[128 + j1], fmaf(r1, W1[64 + j1], fmaf(r0, W1[j1], B1[j1]))));
            ts[j0] = h0; ts[j1] = h1;
            __syncwarp();
            float a0 = B2[j0], a1 = B2[j1];
            #pragma unroll 8
            for (int j = 0; j < 64; j++) {
                float t = ts[j];
                a0 += t * W2[j * 64 + lane];
                a1 += t * W2[j * 64 + lane + 32];
            }
            dst[lane] = a0; dst[lane + 32] = a1;
            __syncwarp();
        }
    }
    __syncthreads();

    // ---- Stage B: scores ----
    for (int it = w; it < 2 * TN * Kc; it += 8) {
        int b = it >> 6, nl = (it >> 4) & (TN - 1), kk = it & 15;
        int nb = idx_s[nl * 16 + kk];
        const float* kp  = g_k + ((size_t)b * Nc + nb) * 64;
        const float* qp  = qs + (b * TN + nl) * 64;
        const float* rap = ra_s + (nl * 16 + kk) * 64;
        float* ts = tsc + w * 64;
        float t0 = tanhf(qp[lane]      - kp[lane]      + rap[lane]);
        float t1 = tanhf(qp[lane + 32] - kp[lane + 32] + rap[lane + 32]);
        ts[lane] = t0; ts[lane + 32] = t1;
        __syncwarp();
        float a0 = bS1s[lane], a1 = bS1s[lane + 32];
        #pragma unroll 8
        for (int a = 0; a < 64; a++) {
            float t = ts[a];
            a0 += t * wS1s[a * 64 + lane];
            a1 += t * wS1s[a * 64 + lane + 32];
        }
        __syncwarp();
        float p = fmaxf(0.f, a0) * wS2s[lane] + fmaxf(0.f, a1) * wS2s[lane + 32];
        #pragma unroll
        for (int o = 16; o; o >>= 1) p += __shfl_xor_sync(~0u, p, o);
        if (lane == 0) sc_s[it] = p + bS2v;
    }
    __syncthreads();

    // ---- Stage C: softmax + context ----
    if (w < 2 * TN) {
        int b = w / TN, nl = w % TN;
        float s = (lane < 16) ? sc_s[(b * TN + nl) * 16 + lane] * 0.125f : -INFINITY;
        float mx = s;
        #pragma unroll
        for (int o = 16; o; o >>= 1) mx = fmaxf(mx, __shfl_xor_sync(~0u, mx, o));
        float e = (lane < 16) ? expf(s - mx) : 0.f;
        float se = e;
        #pragma unroll
        for (int o = 16; o; o >>= 1) se += __shfl_xor_sync(~0u, se, o);
        float wt = e / se;
        if (lane < 16) sc_s[(b * TN + nl) * 16 + lane] = wt;
        __syncwarp();
        float acc0 = 0.f, acc1 = 0.f;
        #pragma unroll
        for (int kk = 0; kk < 16; kk++) {
            float ww = sc_s[(b * TN + nl) * 16 + kk];
            int nb = idx_s[nl * 16 + kk];
            const float* vp  = g_v + ((size_t)b * Nc + nb) * 64;
            const float* rvp = rv_s + (nl * 16 + kk) * 64;
            acc0 += ww * (vp[lane]      + rvp[lane]);
            acc1 += ww * (vp[lane + 32] + rvp[lane + 32]);
        }
        size_t obase = ((size_t)b * Nc + nbase + nl) * 64;
        g_ctx[obase + lane] = acc0;
        g_ctx[obase + lane + 32] = acc1;
    }
}

// ============================================================
// Kernel 3: x1 = x + ctx@Wo + bo ; h2 = LN2(x1)
// ============================================================
__global__ void k_wo_ln2(const float* __restrict__ x,
                         const float* __restrict__ Wo, const float* __restrict__ bo,
                         const float* __restrict__ g2, const float* __restrict__ b2) {
    __shared__ float cs[R1][64];
    __shared__ float x1s[R1][Dc];
    const int row0 = blockIdx.x * R1;
    const int tid = threadIdx.x, lane = tid & 31, w = tid >> 5;

    for (int i = tid; i < R1 * 64; i += 256)
        cs[i >> 6][i & 63] = g_ctx[(size_t)row0 * 64 + i];
    __syncthreads();

    const int col = tid;
    float acc[R1];
    #pragma unroll
    for (int r = 0; r < R1; r++) acc[r] = 0.f;
    #pragma unroll 4
    for (int v = 0; v < 64; v++) {
        float wv = Wo[v * Dc + col];
        #pragma unroll
        for (int r = 0; r < R1; r++) acc[r] += cs[r][v] * wv;
    }
    float bov = bo[col];
    #pragma unroll
    for (int r = 0; r < R1; r++) {
        float val = x[(size_t)(row0 + r) * Dc + col] + acc[r] + bov;
        x1s[r][col] = val;
        g_x1[(size_t)(row0 + r) * Dc + col] = val;
    }
    __syncthreads();

    #pragma unroll
    for (int rr = 0; rr < 2; rr++) {
        int r = w * 2 + rr;
        float s = 0.f;
        #pragma unroll
        for (int i = 0; i < Dc / 32; i++) s += x1s[r][lane + 32 * i];
        #pragma unroll
        for (int o = 16; o; o >>= 1) s += __shfl_xor_sync(~0u, s, o);
        float m = s * (1.0f / Dc);
        float v = 0.f;
        #pragma unroll
        for (int i = 0; i < Dc / 32; i++) { float d = x1s[r][lane + 32 * i] - m; v += d * d; }
        #pragma unroll
        for (int o = 16; o; o >>= 1) v += __shfl_xor_sync(~0u, v, o);
        float rstd = rsqrtf(v * (1.0f / Dc) + 1e-5f);
        #pragma unroll
        for (int i = 0; i < Dc / 32; i++) {
            int d = lane + 32 * i;
            g_h2[(size_t)(row0 + r) * Dc + d] = (x1s[r][d] - m) * rstd * g2[d] + b2[d];
        }
    }
}

// ============================================================
// Kernel 4: out = x1 + gelu(h2@Wf1+bf1)@Wf2 + bf2
// ============================================================
__global__ void k_ffn(const float* __restrict__ Wf1, const float* __restrict__ bf1,
                      const float* __restrict__ Wf2, const float* __restrict__ bf2,
                      float* __restrict__ out) {
    __shared__ float h2s[R1][Dc];   // 16KB
    __shared__ float hid[R1][Hc];   // 32KB
    const int row0 = blockIdx.x * R1;
    const int tid = threadIdx.x;

    for (int i = tid; i < R1 * Dc; i += 256)
        h2s[i >> 8][i & 255] = g_h2[(size_t)row0 * Dc + i];
    __syncthreads();

    {   // phase 1: hidden = gelu(h2 @ Wf1 + bf1), 2 cols/thread
        float acc0[R1], acc1[R1];
        #pragma unroll
        for (int r = 0; r < R1; r++) { acc0[r] = 0.f; acc1[r] = 0.f; }
        const int j0 = tid, j1 = tid + 256;
        #pragma unroll 2
        for (int d = 0; d < Dc; d++) {
            float w0 = Wf1[d * Hc + j0];
            float w1 = Wf1[d * Hc + j1];
            #pragma unroll
            for (int r = 0; r < R1; r++) {
                float h = h2s[r][d];
                acc0[r] += h * w0;
                acc1[r] += h * w1;
            }
        }
        float bb0 = bf1[j0], bb1 = bf1[j1];
        #pragma unroll
        for (int r = 0; r < R1; r++) {
            float z0 = acc0[r] + bb0;
            float z1 = acc1[r] + bb1;
            hid[r][j0] = 0.5f * z0 * (1.f + erff(z0 * 0.70710678118654752f));
            hid[r][j1] = 0.5f * z1 * (1.f + erff(z1 * 0.70710678118654752f));
        }
    }
    __syncthreads();

    {   // phase 2: out = x1 + hidden @ Wf2 + bf2
        float acc[R1];
        #pragma unroll
        for (int r = 0; r < R1; r++) acc[r] = 0.f;
        const int o = tid;
        #pragma unroll 4
        for (int j = 0; j < Hc; j++) {
            float wv = Wf2[j * Dc + o];
            #pragma unroll
            for (int r = 0; r < R1; r++) acc[r] += hid[r][j] * wv;
        }
        float bb = bf2[o];
        #pragma unroll
        for (int r = 0; r < R1; r++)
            out[(size_t)(row0 + r) * Dc + o] = g_x1[(size_t)(row0 + r) * Dc + o] + acc[r] + bb;
    }
}

// ============================================================
extern "C" void kernel_launch(void* const* d_in, const int* in_sizes, int n_in,
                              void* d_out, int out_size) {
    const float* x       = (const float*)d_in[0];
    const int*   knn_idx = (const int*)  d_in[1];
    const float* rel     = (const float*)d_in[2];
    const float* g1 = (const float*)d_in[3];
    const float* b1 = (const float*)d_in[4];
    const float* g2 = (const float*)d_in[5];
    const float* b2 = (const float*)d_in[6];
    const float* Wq = (const float*)d_in[7];
    const float* bq = (const float*)d_in[8];
    const float* Wk = (const float*)d_in[9];
    const float* bk = (const float*)d_in[10];
    const float* Wv = (const float*)d_in[11];
    const float* bv = (const float*)d_in[12];
    const float* Wo = (const float*)d_in[13];
    const float* bo = (const float*)d_in[14];
    const float* Wpa1 = (const float*)d_in[15];
    const float* bpa1 = (const float*)d_in[16];
    const float* Wpa2 = (const float*)d_in[17];
    const float* bpa2 = (const float*)d_in[18];
    const float* Wpv1 = (const float*)d_in[19];
    const float* bpv1 = (const float*)d_in[20];
    const float* Wpv2 = (const float*)d_in[21];
    const float* bpv2 = (const float*)d_in[22];
    const float* Ws1  = (const float*)d_in[23];
    const float* bs1  = (const float*)d_in[24];
    const float* Ws2  = (const float*)d_in[25];
    const float* bs2  = (const float*)d_in[26];
    const float* Wf1  = (const float*)d_in[27];
    const float* bf1  = (const float*)d_in[28];
    const float* Wf2  = (const float*)d_in[29];
    const float* bf2  = (const float*)d_in[30];
    float* out = (float*)d_out;

    const int rows = Bc * Nc;

    k_ln1_qkv<<<rows / R1, 256>>>(x, g1, b1, Wq, bq, Wk, bk, Wv, bv);

    const int smem2 = 90112;
    cudaFuncSetAttribute(k_attn, cudaFuncAttributeMaxDynamicSharedMemorySize, smem2);
    k_attn<<<Nc / TN, 256, smem2>>>(knn_idx, rel,
                                    Wpa1, bpa1, Wpa2, bpa2,
                                    Wpv1, bpv1, Wpv2, bpv2,
                                    Ws1, bs1, Ws2, bs2);

    k_wo_ln2<<<rows / R1, 256>>>(x, Wo, bo, g2, b2);

    k_ffn<<<rows / R1, 256>>>(Wf1, bf1, Wf2, bf2, out);
}

// round 3
// speedup vs baseline: 1.1850x; 1.1850x over previous
#include <cuda_runtime.h>
#include <mma.h>
#include <math.h>

using namespace nvcuda;

// Problem constants
#define Bc 2
#define Nc 32768
#define Kc 16
#define Dc 256
#define Ac 64
#define Vc 64
#define Hc 512
#define Mrows (Bc * Nc)   // 65536

#define R1 16
#define TN 4

// -------- scratch (device globals; no cudaMalloc allowed) --------
__device__ float g_ln [(size_t)Mrows * Dc];
__device__ float g_q  [(size_t)Mrows * Ac];
__device__ float g_k  [(size_t)Mrows * Ac];
__device__ float g_v  [(size_t)Mrows * Vc];
__device__ float g_ctx[(size_t)Mrows * Vc];
__device__ float g_x1 [(size_t)Mrows * Dc];
__device__ float g_h2 [(size_t)Mrows * Dc];
__device__ float g_hid[(size_t)Mrows * Hc];

__device__ __forceinline__ float fast_tanh(float x) {
    float y;
    asm("tanh.approx.f32 %0, %1;" : "=f"(y) : "f"(x));
    return y;
}

// ============================================================
// LayerNorm kernel: out = LN(in) * g + b.  one warp per row.
// ============================================================
__global__ void k_ln(const float* __restrict__ in,
                     const float* __restrict__ g, const float* __restrict__ b,
                     float* __restrict__ out) {
    const int row = blockIdx.x * 8 + (threadIdx.x >> 5);
    const int lane = threadIdx.x & 31;
    const float* p = in + (size_t)row * Dc;
    float v[8];
    #pragma unroll
    for (int i = 0; i < 8; i++) v[i] = p[lane + 32 * i];
    float s = 0.f;
    #pragma unroll
    for (int i = 0; i < 8; i++) s += v[i];
    #pragma unroll
    for (int o = 16; o; o >>= 1) s += __shfl_xor_sync(~0u, s, o);
    float m = s * (1.0f / Dc);
    float var = 0.f;
    #pragma unroll
    for (int i = 0; i < 8; i++) { float d = v[i] - m; var += d * d; }
    #pragma unroll
    for (int o = 16; o; o >>= 1) var += __shfl_xor_sync(~0u, var, o);
    float rstd = rsqrtf(var * (1.0f / Dc) + 1e-5f);
    float* q = out + (size_t)row * Dc;
    #pragma unroll
    for (int i = 0; i < 8; i++) {
        int d = lane + 32 * i;
        q[d] = (v[i] - m) * rstd * g[d] + b[d];
    }
}

// ============================================================
// Generic tf32 wmma GEMM: C[M,N] = act(A[M,K] @ B[K,N] + bias) (+ Res)
// block 256 thr (8 warps, 4x2), tile 128x64, k-chunk 32.
// ============================================================
#define BM 128
#define BN 64
#define BK 32
#define LDA 36
#define LDB 68
#define LDE 36

template<int ACT, bool HAS_RES>
__global__ void gemm_tf32(const float* __restrict__ A, const float* __restrict__ B,
                          const float* __restrict__ bias, const float* __restrict__ Res,
                          float* __restrict__ C, int M, int N, int K) {
    __shared__ float smem[9216];   // 36 KB: load buffers / epilogue staging (aliased)
    float* As = smem;              // 128 * 36 = 4608
    float* Bs = smem + 4608;       // 32 * 68  = 2176

    const int tid = threadIdx.x;
    const int warp = tid >> 5, lane = tid & 31;
    const int wm = warp & 3;       // 0..3
    const int wn = warp >> 2;      // 0..1
    const int row0 = blockIdx.x * BM;
    const int col0 = blockIdx.y * BN;

    wmma::fragment<wmma::accumulator, 16, 16, 8, float> cf[2][2];
    #pragma unroll
    for (int i = 0; i < 2; i++)
        #pragma unroll
        for (int j = 0; j < 2; j++) wmma::fill_fragment(cf[i][j], 0.f);

    for (int k0 = 0; k0 < K; k0 += BK) {
        // load A tile (BM x BK), float4
        #pragma unroll
        for (int i = tid; i < BM * BK / 4; i += 256) {
            int r = i >> 3, c4 = i & 7;
            float4 v = *(const float4*)(A + (size_t)(row0 + r) * K + k0 + c4 * 4);
            float* d = &As[r * LDA + c4 * 4];
            d[0] = v.x; d[1] = v.y; d[2] = v.z; d[3] = v.w;
        }
        // load B tile (BK x BN), float4
        #pragma unroll
        for (int i = tid; i < BK * BN / 4; i += 256) {
            int r = i >> 4, c4 = i & 15;
            float4 v = *(const float4*)(B + (size_t)(k0 + r) * N + col0 + c4 * 4);
            float* d = &Bs[r * LDB + c4 * 4];
            d[0] = v.x; d[1] = v.y; d[2] = v.z; d[3] = v.w;
        }
        __syncthreads();

        #pragma unroll
        for (int kk = 0; kk < BK; kk += 8) {
            wmma::fragment<wmma::matrix_a, 16, 16, 8, wmma::precision::tf32, wmma::row_major> af[2];
            wmma::fragment<wmma::matrix_b, 16, 16, 8, wmma::precision::tf32, wmma::row_major> bf[2];
            #pragma unroll
            for (int i = 0; i < 2; i++) {
                wmma::load_matrix_sync(af[i], &As[(wm * 32 + i * 16) * LDA + kk], LDA);
                #pragma unroll
                for (int t = 0; t < af[i].num_elements; t++)
                    af[i].x[t] = wmma::__float_to_tf32(af[i].x[t]);
            }
            #pragma unroll
            for (int j = 0; j < 2; j++) {
                wmma::load_matrix_sync(bf[j], &Bs[kk * LDB + wn * 32 + j * 16], LDB);
                #pragma unroll
                for (int t = 0; t < bf[j].num_elements; t++)
                    bf[j].x[t] = wmma::__float_to_tf32(bf[j].x[t]);
            }
            #pragma unroll
            for (int i = 0; i < 2; i++)
                #pragma unroll
                for (int j = 0; j < 2; j++)
                    wmma::mma_sync(cf[i][j], af[i], bf[j], cf[i][j]);
        }
        __syncthreads();
    }

    // epilogue: stage each warp's 32x32 tile in smem, then bias/act/res + store
    float* Ep = smem + warp * (32 * LDE);
    #pragma unroll
    for (int i = 0; i < 2; i++)
        #pragma unroll
        for (int j = 0; j < 2; j++)
            wmma::store_matrix_sync(&Ep[i * 16 * LDE + j * 16], cf[i][j], LDE, wmma::mem_row_major);
    __syncwarp();

    const int gr0 = row0 + wm * 32;
    const int gc  = col0 + wn * 32 + lane;
    const float bv = bias[gc];
    #pragma unroll 4
    for (int r = 0; r < 32; r++) {
        float z = Ep[r * LDE + lane] + bv;
        if (ACT == 1) z = 0.5f * z * (1.f + erff(z * 0.70710678118654752f));
        if (HAS_RES) z += Res[(size_t)(gr0 + r) * N + gc];
        C[(size_t)(gr0 + r) * N + gc] = z;
    }
}

// ============================================================
// Attention kernel: ra/rv recompute + scores + softmax + ctx
// grid = N/TN, 256 threads (8 warps), dynamic smem ~88KB
// ============================================================
__global__ void k_attn(const int* __restrict__ knn_idx,
                       const float* __restrict__ rel,
                       const float* __restrict__ Wpa1, const float* __restrict__ bpa1,
                       const float* __restrict__ Wpa2, const float* __restrict__ bpa2,
                       const float* __restrict__ Wpv1, const float* __restrict__ bpv1,
                       const float* __restrict__ Wpv2, const float* __restrict__ bpv2,
                       const float* __restrict__ Ws1,  const float* __restrict__ bs1,
                       const float* __restrict__ Ws2,  const float* __restrict__ bs2) {
    extern __shared__ float sm[];
    float* wPa1 = sm;              // 192
    float* bPa1 = wPa1 + 192;      // 64
    float* wPa2 = bPa1 + 64;       // 4096
    float* bPa2 = wPa2 + 4096;     // 64
    float* wPv1 = bPa2 + 64;       // 192
    float* bPv1 = wPv1 + 192;      // 64
    float* wPv2 = bPv1 + 64;       // 4096
    float* bPv2 = wPv2 + 4096;     // 64
    float* wS1s = bPv2 + 64;       // 4096
    float* bS1s = wS1s + 4096;     // 64
    float* wS2s = bS1s + 64;       // 64
    float* qs   = wS2s + 64;       // 512
    float* ra_s = qs + 512;        // 4096
    float* rv_s = ra_s + 4096;     // 4096
    float* tsc  = rv_s + 4096;     // 512
    float* sc_s = tsc + 512;       // 128
    int*   idx_s = (int*)(sc_s + 128); // 64

    const int tid = threadIdx.x, lane = tid & 31, w = tid >> 5;
    const int nbase = blockIdx.x * TN;
    const int j0 = 2 * lane, j1 = 2 * lane + 1;

    for (int i = tid; i < 192;  i += 256) { wPa1[i] = Wpa1[i]; wPv1[i] = Wpv1[i]; }
    for (int i = tid; i < 64;   i += 256) {
        bPa1[i] = bpa1[i]; bPa2[i] = bpa2[i];
        bPv1[i] = bpv1[i]; bPv2[i] = bpv2[i];
        bS1s[i] = bs1[i];  wS2s[i] = Ws2[i];
    }
    for (int i = tid; i < 4096; i += 256) { wPa2[i] = Wpa2[i]; wPv2[i] = Wpv2[i]; wS1s[i] = Ws1[i]; }
    for (int i = tid; i < 2 * TN * 64; i += 256) {
        int b = i >> 8, nl = (i >> 6) & (TN - 1), a = i & 63;
        qs[i] = g_q[((size_t)b * Nc + nbase + nl) * 64 + a];
    }
    for (int i = tid; i < TN * 16; i += 256)
        idx_s[i] = knn_idx[(size_t)(nbase + (i >> 4)) * Kc + (i & 15)];
    const float bS2v = bs2[0];
    __syncthreads();

    // ---- Stage A: ra/rv (shared across batches) ----
    for (int it = w; it < TN * Kc; it += 8) {
        int nl = it >> 4, kk = it & 15;
        const float* rp = rel + ((size_t)(nbase + nl) * Kc + kk) * 3;
        float r0 = rp[0], r1 = rp[1], r2 = rp[2];
        float* ts = tsc + w * 64;
        #pragma unroll
        for (int pp = 0; pp < 2; pp++) {
            const float* W1 = pp ? wPv1 : wPa1;
            const float* B1 = pp ? bPv1 : bPa1;
            const float* W2 = pp ? wPv2 : wPa2;
            const float* B2 = pp ? bPv2 : bPa2;
            float* dst = (pp ? rv_s : ra_s) + (nl * Kc + kk) * 64;
            float h0 = fmaxf(0.f, fmaf(r2, W1[128 + j0], fmaf(r1, W1[64 + j0], fmaf(r0, W1[j0], B1[j0]))));
            float h1 = fmaxf(0.f, fmaf(r2, W1[128 + j1], fmaf(r1, W1[64 + j1], fmaf(r0, W1[j1], B1[j1]))));
            *(float2*)(ts + j0) = make_float2(h0, h1);
            __syncwarp();
            float a0 = B2[j0], a1 = B2[j1];
            #pragma unroll 8
            for (int j = 0; j < 64; j++) {
                float t = ts[j];
                float2 wv = *(const float2*)(W2 + j * 64 + j0);
                a0 += t * wv.x;
                a1 += t * wv.y;
            }
            *(float2*)(dst + j0) = make_float2(a0, a1);
            __syncwarp();
        }
    }
    __syncthreads();

    // ---- Stage B: scores ----
    for (int it = w; it < 2 * TN * Kc; it += 8) {
        int b = it >> 6, nl = (it >> 4) & (TN - 1), kk = it & 15;
        int nb = idx_s[nl * 16 + kk];
        const float* kp  = g_k + ((size_t)b * Nc + nb) * 64;
        const float* qp  = qs + (b * TN + nl) * 64;
        const float* rap = ra_s + (nl * 16 + kk) * 64;
        float* ts = tsc + w * 64;
        float2 qv = *(const float2*)(qp + j0);
        float2 kv = *(const float2*)(kp + j0);
        float2 rv = *(const float2*)(rap + j0);
        float t0 = fast_tanh(qv.x - kv.x + rv.x);
        float t1 = fast_tanh(qv.y - kv.y + rv.y);
        *(float2*)(ts + j0) = make_float2(t0, t1);
        __syncwarp();
        float a0 = bS1s[j0], a1 = bS1s[j1];
        #pragma unroll 8
        for (int a = 0; a < 64; a++) {
            float t = ts[a];
            float2 wv = *(const float2*)(wS1s + a * 64 + j0);
            a0 += t * wv.x;
            a1 += t * wv.y;
        }
        __syncwarp();
        float p = fmaxf(0.f, a0) * wS2s[j0] + fmaxf(0.f, a1) * wS2s[j1];
        #pragma unroll
        for (int o = 16; o; o >>= 1) p += __shfl_xor_sync(~0u, p, o);
        if (lane == 0) sc_s[it] = p + bS2v;
    }
    __syncthreads();

    // ---- Stage C: softmax + context ----
    if (w < 2 * TN) {
        int b = w / TN, nl = w % TN;
        float s = (lane < 16) ? sc_s[(b * TN + nl) * 16 + lane] * 0.125f : -INFINITY;
        float mx = s;
        #pragma unroll
        for (int o = 16; o; o >>= 1) mx = fmaxf(mx, __shfl_xor_sync(~0u, mx, o));
        float e = (lane < 16) ? __expf(s - mx) : 0.f;
        float se = e;
        #pragma unroll
        for (int o = 16; o; o >>= 1) se += __shfl_xor_sync(~0u, se, o);
        float wt = e / se;
        if (lane < 16) sc_s[(b * TN + nl) * 16 + lane] = wt;
        __syncwarp();
        float acc0 = 0.f, acc1 = 0.f;
        #pragma unroll
        for (int kk = 0; kk < 16; kk++) {
            float ww = sc_s[(b * TN + nl) * 16 + kk];
            int nb = idx_s[nl * 16 + kk];
            const float* vp  = g_v + ((size_t)b * Nc + nb) * 64;
            const float* rvp = rv_s + (nl * 16 + kk) * 64;
            acc0 += ww * (vp[lane]      + rvp[lane]);
            acc1 += ww * (vp[lane + 32] + rvp[lane + 32]);
        }
        size_t obase = ((size_t)b * Nc + nbase + nl) * 64;
        g_ctx[obase + lane] = acc0;
        g_ctx[obase + lane + 32] = acc1;
    }
}

// ============================================================
// Kernel 3: x1 = x + ctx@Wo + bo ; h2 = LN2(x1)
// ============================================================
__global__ void k_wo_ln2(const float* __restrict__ x,
                         const float* __restrict__ Wo, const float* __restrict__ bo,
                         const float* __restrict__ g2, const float* __restrict__ b2) {
    __shared__ float cs[R1][64];
    __shared__ float x1s[R1][Dc];
    const int row0 = blockIdx.x * R1;
    const int tid = threadIdx.x, lane = tid & 31, w = tid >> 5;

    for (int i = tid; i < R1 * 64; i += 256)
        cs[i >> 6][i & 63] = g_ctx[(size_t)row0 * 64 + i];
    __syncthreads();

    const int col = tid;
    float acc[R1];
    #pragma unroll
    for (int r = 0; r < R1; r++) acc[r] = 0.f;
    #pragma unroll 4
    for (int v = 0; v < 64; v++) {
        float wv = Wo[v * Dc + col];
        #pragma unroll
        for (int r = 0; r < R1; r++) acc[r] += cs[r][v] * wv;
    }
    float bov = bo[col];
    #pragma unroll
    for (int r = 0; r < R1; r++) {
        float val = x[(size_t)(row0 + r) * Dc + col] + acc[r] + bov;
        x1s[r][col] = val;
        g_x1[(size_t)(row0 + r) * Dc + col] = val;
    }
    __syncthreads();

    #pragma unroll
    for (int rr = 0; rr < 2; rr++) {
        int r = w * 2 + rr;
        float s = 0.f;
        #pragma unroll
        for (int i = 0; i < Dc / 32; i++) s += x1s[r][lane + 32 * i];
        #pragma unroll
        for (int o = 16; o; o >>= 1) s += __shfl_xor_sync(~0u, s, o);
        float m = s * (1.0f / Dc);
        float v = 0.f;
        #pragma unroll
        for (int i = 0; i < Dc / 32; i++) { float d = x1s[r][lane + 32 * i] - m; v += d * d; }
        #pragma unroll
        for (int o = 16; o; o >>= 1) v += __shfl_xor_sync(~0u, v, o);
        float rstd = rsqrtf(v * (1.0f / Dc) + 1e-5f);
        #pragma unroll
        for (int i = 0; i < Dc / 32; i++) {
            int d = lane + 32 * i;
            g_h2[(size_t)(row0 + r) * Dc + d] = (x1s[r][d] - m) * rstd * g2[d] + b2[d];
        }
    }
}

// ============================================================
extern "C" void kernel_launch(void* const* d_in, const int* in_sizes, int n_in,
                              void* d_out, int out_size) {
    const float* x       = (const float*)d_in[0];
    const int*   knn_idx = (const int*)  d_in[1];
    const float* rel     = (const float*)d_in[2];
    const float* g1 = (const float*)d_in[3];
    const float* b1 = (const float*)d_in[4];
    const float* g2 = (const float*)d_in[5];
    const float* b2 = (const float*)d_in[6];
    const float* Wq = (const float*)d_in[7];
    const float* bq = (const float*)d_in[8];
    const float* Wk = (const float*)d_in[9];
    const float* bk = (const float*)d_in[10];
    const float* Wv = (const float*)d_in[11];
    const float* bv = (const float*)d_in[12];
    const float* Wo = (const float*)d_in[13];
    const float* bo = (const float*)d_in[14];
    const float* Wpa1 = (const float*)d_in[15];
    const float* bpa1 = (const float*)d_in[16];
    const float* Wpa2 = (const float*)d_in[17];
    const float* bpa2 = (const float*)d_in[18];
    const float* Wpv1 = (const float*)d_in[19];
    const float* bpv1 = (const float*)d_in[20];
    const float* Wpv2 = (const float*)d_in[21];
    const float* bpv2 = (const float*)d_in[22];
    const float* Ws1  = (const float*)d_in[23];
    const float* bs1  = (const float*)d_in[24];
    const float* Ws2  = (const float*)d_in[25];
    const float* bs2  = (const float*)d_in[26];
    const float* Wf1  = (const float*)d_in[27];
    const float* bf1  = (const float*)d_in[28];
    const float* Wf2  = (const float*)d_in[29];
    const float* bf2  = (const float*)d_in[30];
    float* out = (float*)d_out;

    float *p_ln, *p_q, *p_k, *p_v, *p_x1, *p_h2, *p_hid;
    cudaGetSymbolAddress((void**)&p_ln,  g_ln);
    cudaGetSymbolAddress((void**)&p_q,   g_q);
    cudaGetSymbolAddress((void**)&p_k,   g_k);
    cudaGetSymbolAddress((void**)&p_v,   g_v);
    cudaGetSymbolAddress((void**)&p_x1,  g_x1);
    cudaGetSymbolAddress((void**)&p_h2,  g_h2);
    cudaGetSymbolAddress((void**)&p_hid, g_hid);

    // 1. LN1
    k_ln<<<Mrows / 8, 256>>>(x, g1, b1, p_ln);

    // 2. QKV projections (tf32 tensor cores)
    gemm_tf32<0, false><<<dim3(Mrows / BM, 1), 256>>>(p_ln, Wq, bq, nullptr, p_q, Mrows, 64, Dc);
    gemm_tf32<0, false><<<dim3(Mrows / BM, 1), 256>>>(p_ln, Wk, bk, nullptr, p_k, Mrows, 64, Dc);
    gemm_tf32<0, false><<<dim3(Mrows / BM, 1), 256>>>(p_ln, Wv, bv, nullptr, p_v, Mrows, 64, Dc);

    // 3. attention
    const int smem2 = 90112;
    cudaFuncSetAttribute(k_attn, cudaFuncAttributeMaxDynamicSharedMemorySize, smem2);
    k_attn<<<Nc / TN, 256, smem2>>>(knn_idx, rel,
                                    Wpa1, bpa1, Wpa2, bpa2,
                                    Wpv1, bpv1, Wpv2, bpv2,
                                    Ws1, bs1, Ws2, bs2);

    // 4. Wo + residual + LN2
    k_wo_ln2<<<Mrows / R1, 256>>>(x, Wo, bo, g2, b2);

    // 5. FFN (tf32 tensor cores)
    gemm_tf32<1, false><<<dim3(Mrows / BM, Hc / BN), 256>>>(p_h2, Wf1, bf1, nullptr, p_hid, Mrows, Hc, Dc);
    gemm_tf32<0, true ><<<dim3(Mrows / BM, Dc / BN), 256>>>(p_hid, Wf2, bf2, p_x1, out, Mrows, Dc, Hc);
}

// round 4
// speedup vs baseline: 1.5305x; 1.2915x over previous
#include <cuda_runtime.h>
#include <mma.h>
#include <math.h>

using namespace nvcuda;

// Problem constants
#define Bc 2
#define Nc 32768
#define Kc 16
#define Dc 256
#define Ac 64
#define Vc 64
#define Hc 512
#define Mrows (Bc * Nc)   // 65536

#define R1 16
#define TN 2              // points per attention block

// -------- scratch (device globals) --------
__device__ float g_ln [(size_t)Mrows * Dc];
__device__ float g_q  [(size_t)Mrows * Ac];
__device__ float g_k  [(size_t)Mrows * Ac];
__device__ float g_v  [(size_t)Mrows * Vc];
__device__ float g_ctx[(size_t)Mrows * Vc];
__device__ float g_x1 [(size_t)Mrows * Dc];
__device__ float g_h2 [(size_t)Mrows * Dc];
__device__ float g_hid[(size_t)Mrows * Hc];

__device__ __forceinline__ float fast_tanh(float x) {
    float y;
    asm("tanh.approx.f32 %0, %1;" : "=f"(y) : "f"(x));
    return y;
}

// ============================================================
// LayerNorm: out = LN(in)*g + b.  one warp per row.
// ============================================================
__global__ void k_ln(const float* __restrict__ in,
                     const float* __restrict__ g, const float* __restrict__ b,
                     float* __restrict__ out) {
    const int row = blockIdx.x * 8 + (threadIdx.x >> 5);
    const int lane = threadIdx.x & 31;
    const float* p = in + (size_t)row * Dc;
    float v[8];
    #pragma unroll
    for (int i = 0; i < 8; i++) v[i] = p[lane + 32 * i];
    float s = 0.f;
    #pragma unroll
    for (int i = 0; i < 8; i++) s += v[i];
    #pragma unroll
    for (int o = 16; o; o >>= 1) s += __shfl_xor_sync(~0u, s, o);
    float m = s * (1.0f / Dc);
    float var = 0.f;
    #pragma unroll
    for (int i = 0; i < 8; i++) { float d = v[i] - m; var += d * d; }
    #pragma unroll
    for (int o = 16; o; o >>= 1) var += __shfl_xor_sync(~0u, var, o);
    float rstd = rsqrtf(var * (1.0f / Dc) + 1e-5f);
    float* q = out + (size_t)row * Dc;
    #pragma unroll
    for (int i = 0; i < 8; i++) {
        int d = lane + 32 * i;
        q[d] = (v[i] - m) * rstd * g[d] + b[d];
    }
}

// ============================================================
// tf32 wmma GEMM core: C = act(A@B + bias) (+Res)
// tile 128x64, k-chunk 32, 8 warps (4x2)
// ============================================================
#define BM 128
#define BN 64
#define BK 32
#define LDA 36
#define LDB 68
#define LDE 36

template<int ACT, bool HAS_RES>
__device__ __forceinline__ void gemm_core(const float* __restrict__ A, const float* __restrict__ B,
                                          const float* __restrict__ bias, const float* __restrict__ Res,
                                          float* __restrict__ C, int N, int K, int row0, int col0) {
    __shared__ float smem[9216];
    float* As = smem;
    float* Bs = smem + 4608;

    const int tid = threadIdx.x;
    const int warp = tid >> 5, lane = tid & 31;
    const int wm = warp & 3;
    const int wn = warp >> 2;

    wmma::fragment<wmma::accumulator, 16, 16, 8, float> cf[2][2];
    #pragma unroll
    for (int i = 0; i < 2; i++)
        #pragma unroll
        for (int j = 0; j < 2; j++) wmma::fill_fragment(cf[i][j], 0.f);

    for (int k0 = 0; k0 < K; k0 += BK) {
        #pragma unroll
        for (int i = tid; i < BM * BK / 4; i += 256) {
            int r = i >> 3, c4 = i & 7;
            float4 v = *(const float4*)(A + (size_t)(row0 + r) * K + k0 + c4 * 4);
            float* d = &As[r * LDA + c4 * 4];
            d[0] = v.x; d[1] = v.y; d[2] = v.z; d[3] = v.w;
        }
        #pragma unroll
        for (int i = tid; i < BK * BN / 4; i += 256) {
            int r = i >> 4, c4 = i & 15;
            float4 v = *(const float4*)(B + (size_t)(k0 + r) * N + col0 + c4 * 4);
            float* d = &Bs[r * LDB + c4 * 4];
            d[0] = v.x; d[1] = v.y; d[2] = v.z; d[3] = v.w;
        }
        __syncthreads();

        #pragma unroll
        for (int kk = 0; kk < BK; kk += 8) {
            wmma::fragment<wmma::matrix_a, 16, 16, 8, wmma::precision::tf32, wmma::row_major> af[2];
            wmma::fragment<wmma::matrix_b, 16, 16, 8, wmma::precision::tf32, wmma::row_major> bf[2];
            #pragma unroll
            for (int i = 0; i < 2; i++) {
                wmma::load_matrix_sync(af[i], &As[(wm * 32 + i * 16) * LDA + kk], LDA);
                #pragma unroll
                for (int t = 0; t < af[i].num_elements; t++)
                    af[i].x[t] = wmma::__float_to_tf32(af[i].x[t]);
            }
            #pragma unroll
            for (int j = 0; j < 2; j++) {
                wmma::load_matrix_sync(bf[j], &Bs[kk * LDB + wn * 32 + j * 16], LDB);
                #pragma unroll
                for (int t = 0; t < bf[j].num_elements; t++)
                    bf[j].x[t] = wmma::__float_to_tf32(bf[j].x[t]);
            }
            #pragma unroll
            for (int i = 0; i < 2; i++)
                #pragma unroll
                for (int j = 0; j < 2; j++)
                    wmma::mma_sync(cf[i][j], af[i], bf[j], cf[i][j]);
        }
        __syncthreads();
    }

    float* Ep = smem + warp * (32 * LDE);
    #pragma unroll
    for (int i = 0; i < 2; i++)
        #pragma unroll
        for (int j = 0; j < 2; j++)
            wmma::store_matrix_sync(&Ep[i * 16 * LDE + j * 16], cf[i][j], LDE, wmma::mem_row_major);
    __syncwarp();

    const int gr0 = row0 + wm * 32;
    const int gc  = col0 + wn * 32 + lane;
    const float bv = bias[gc];
    #pragma unroll 4
    for (int r = 0; r < 32; r++) {
        float z = Ep[r * LDE + lane] + bv;
        if (ACT == 1) z = 0.5f * z * (1.f + erff(z * 0.70710678118654752f));
        if (HAS_RES) z += Res[(size_t)(gr0 + r) * N + gc];
        C[(size_t)(gr0 + r) * N + gc] = z;
    }
}

// fused QKV: grid.y = {0,1,2} selects projection
__global__ void __launch_bounds__(256) k_qkv(const float* __restrict__ A,
                      const float* __restrict__ Wq, const float* __restrict__ bq,
                      const float* __restrict__ Wk, const float* __restrict__ bk,
                      const float* __restrict__ Wv, const float* __restrict__ bv) {
    const float* B; const float* bias; float* C;
    if (blockIdx.y == 0)      { B = Wq; bias = bq; C = g_q; }
    else if (blockIdx.y == 1) { B = Wk; bias = bk; C = g_k; }
    else                      { B = Wv; bias = bv; C = g_v; }
    gemm_core<0, false>(A, B, bias, nullptr, C, 64, Dc, blockIdx.x * BM, 0);
}

__global__ void __launch_bounds__(256) k_ffn1(const float* __restrict__ A, const float* __restrict__ B,
                       const float* __restrict__ bias, float* __restrict__ C) {
    gemm_core<1, false>(A, B, bias, nullptr, C, Hc, Dc, blockIdx.x * BM, blockIdx.y * BN);
}

__global__ void __launch_bounds__(256) k_ffn2(const float* __restrict__ A, const float* __restrict__ B,
                       const float* __restrict__ bias, const float* __restrict__ Res,
                       float* __restrict__ C) {
    gemm_core<0, true>(A, B, bias, Res, C, Dc, Hc, blockIdx.x * BM, blockIdx.y * BN);
}

// ============================================================
// Attention kernel (tensor-core version)
// grid = Nc/TN, 256 threads (8 warps)
// ============================================================
#define LDW 68

__global__ void __launch_bounds__(256) k_attn(
                       const int* __restrict__ knn_idx,
                       const float* __restrict__ rel,
                       const float* __restrict__ Wpa1, const float* __restrict__ bpa1,
                       const float* __restrict__ Wpa2, const float* __restrict__ bpa2,
                       const float* __restrict__ Wpv1, const float* __restrict__ bpv1,
                       const float* __restrict__ Wpv2, const float* __restrict__ bpv2,
                       const float* __restrict__ Ws1,  const float* __restrict__ bs1,
                       const float* __restrict__ Ws2,  const float* __restrict__ bs2) {
    extern __shared__ float sm[];
    float* wPa2 = sm;               // [64][68] = 4352
    float* wPv2 = wPa2 + 4352;      // 4352
    float* wS1s = wPv2 + 4352;      // 4352
    float* wPa1 = wS1s + 4352;      // 192
    float* wPv1 = wPa1 + 192;       // 192
    float* bPa1 = wPv1 + 192;       // 64
    float* bPv1 = bPa1 + 64;        // 64
    float* bPa2 = bPv1 + 64;        // 64
    float* bPv2 = bPa2 + 64;        // 64
    float* bS1s = bPv2 + 64;        // 64
    float* wS2s = bS1s + 64;        // 64
    float* qs   = wS2s + 64;        // 256  (2*TN*64)
    float* rel_s= qs + 256;         // 96   (TN*16*3)
    float* ra_s = rel_s + 96;       // [32][68] = 2176
    float* rv_s = ra_s + 2176;      // 2176
    float* tbuf = rv_s + 2176;      // [64][68] = 4352
    float* sc_s = tbuf + 4352;      // 64
    int*  idx_s = (int*)(sc_s + 64);// 32

    const int tid = threadIdx.x, lane = tid & 31, warp = tid >> 5;
    const int nbase = blockIdx.x * TN;

    // ---- cooperative loads ----
    for (int i = tid; i < 4096; i += 256) {
        int r = i >> 6, c = i & 63;
        wPa2[r * LDW + c] = Wpa2[i];
        wPv2[r * LDW + c] = Wpv2[i];
        wS1s[r * LDW + c] = Ws1[i];
    }
    for (int i = tid; i < 192; i += 256) { wPa1[i] = Wpa1[i]; wPv1[i] = Wpv1[i]; }
    if (tid < 64) {
        bPa1[tid] = bpa1[tid]; bPv1[tid] = bpv1[tid];
        bPa2[tid] = bpa2[tid]; bPv2[tid] = bpv2[tid];
        bS1s[tid] = bs1[tid];  wS2s[tid] = Ws2[tid];
    }
    for (int i = tid; i < 2 * TN * 64; i += 256) {
        int b = i >> 7, nl = (i >> 6) & (TN - 1), a = i & 63;
        qs[i] = g_q[((size_t)b * Nc + nbase + nl) * 64 + a];
    }
    if (tid < TN * Kc * 3) rel_s[tid] = rel[(size_t)nbase * Kc * 3 + tid];
    if (tid < TN * Kc)     idx_s[tid] = knn_idx[(size_t)nbase * Kc + tid];
    const float bS2v = bs2[0];
    __syncthreads();

    // ---- Stage A: ra/rv via wmma (32x64 @ 64x64) ----
    #pragma unroll
    for (int pp = 0; pp < 2; pp++) {
        const float* W1 = pp ? wPv1 : wPa1;
        const float* B1 = pp ? bPv1 : bPa1;
        const float* W2 = pp ? wPv2 : wPa2;
        float* dst = pp ? rv_s : ra_s;

        // build hidden H = relu(rel@W1 + b1) into tbuf rows [0,32)
        for (int i = tid; i < 32 * 64; i += 256) {
            int r = i >> 6, j = i & 63;
            float r0 = rel_s[r * 3], r1 = rel_s[r * 3 + 1], r2 = rel_s[r * 3 + 2];
            float h = fmaf(r2, W1[128 + j], fmaf(r1, W1[64 + j], fmaf(r0, W1[j], B1[j])));
            tbuf[r * LDW + j] = fmaxf(h, 0.f);
        }
        __syncthreads();

        // GEMM: tiles 2x4, warp -> (mt, nt)
        {
            const int mt = warp >> 2, nt = warp & 3;
            wmma::fragment<wmma::accumulator, 16, 16, 8, float> acc;
            wmma::fill_fragment(acc, 0.f);
            #pragma unroll
            for (int kk = 0; kk < 64; kk += 8) {
                wmma::fragment<wmma::matrix_a, 16, 16, 8, wmma::precision::tf32, wmma::row_major> af;
                wmma::fragment<wmma::matrix_b, 16, 16, 8, wmma::precision::tf32, wmma::row_major> bf;
                wmma::load_matrix_sync(af, &tbuf[(mt * 16) * LDW + kk], LDW);
                wmma::load_matrix_sync(bf, &W2[kk * LDW + nt * 16], LDW);
                #pragma unroll
                for (int t = 0; t < af.num_elements; t++) af.x[t] = wmma::__float_to_tf32(af.x[t]);
                #pragma unroll
                for (int t = 0; t < bf.num_elements; t++) bf.x[t] = wmma::__float_to_tf32(bf.x[t]);
                wmma::mma_sync(acc, af, bf, acc);
            }
            __syncthreads();  // all tbuf reads done
            wmma::store_matrix_sync(&dst[(mt * 16) * LDW + nt * 16], acc, LDW, wmma::mem_row_major);
        }
        __syncthreads();
    }

    // ---- Stage B: build t = tanh(q - k + ra + bPa2), rows = 2*TN*Kc = 64 ----
    for (int i = tid; i < 64 * 64; i += 256) {
        int it = i >> 6, a = i & 63;
        int b = it >> 5, nl = (it >> 4) & (TN - 1), kk = it & 15;
        int nb = idx_s[nl * 16 + kk];
        float kv = __ldg(&g_k[((size_t)b * Nc + nb) * 64 + a]);
        float t = qs[(b * TN + nl) * 64 + a] - kv + ra_s[(nl * 16 + kk) * LDW + a] + bPa2[a];
        tbuf[it * LDW + a] = fast_tanh(t);
    }
    __syncthreads();

    // GEMM: u = t @ Ws1  (64x64 @ 64x64), tiles 4x4, 2 per warp
    {
        const int mt = warp >> 1, nt2 = (warp & 1) * 2;
        wmma::fragment<wmma::accumulator, 16, 16, 8, float> acc[2];
        wmma::fill_fragment(acc[0], 0.f);
        wmma::fill_fragment(acc[1], 0.f);
        #pragma unroll
        for (int kk = 0; kk < 64; kk += 8) {
            wmma::fragment<wmma::matrix_a, 16, 16, 8, wmma::precision::tf32, wmma::row_major> af;
            wmma::fragment<wmma::matrix_b, 16, 16, 8, wmma::precision::tf32, wmma::row_major> bf[2];
            wmma::load_matrix_sync(af, &tbuf[(mt * 16) * LDW + kk], LDW);
            #pragma unroll
            for (int t = 0; t < af.num_elements; t++) af.x[t] = wmma::__float_to_tf32(af.x[t]);
            #pragma unroll
            for (int j = 0; j < 2; j++) {
                wmma::load_matrix_sync(bf[j], &wS1s[kk * LDW + (nt2 + j) * 16], LDW);
                #pragma unroll
                for (int t = 0; t < bf[j].num_elements; t++) bf[j].x[t] = wmma::__float_to_tf32(bf[j].x[t]);
                wmma::mma_sync(acc[j], af, bf[j], acc[j]);
            }
        }
        __syncthreads();  // all tbuf reads done; safe to overwrite with u
        wmma::store_matrix_sync(&tbuf[(mt * 16) * LDW + nt2 * 16],        acc[0], LDW, wmma::mem_row_major);
        wmma::store_matrix_sync(&tbuf[(mt * 16) * LDW + (nt2 + 1) * 16],  acc[1], LDW, wmma::mem_row_major);
    }
    __syncthreads();

    // score: sc[it] = sum_a relu(u + bS1) * wS2 + bs2; warp handles 8 rows
    {
        const int j0 = 2 * lane, j1 = 2 * lane + 1;
        float w0 = wS2s[j0], w1 = wS2s[j1];
        float bb0 = bS1s[j0], bb1 = bS1s[j1];
        #pragma unroll
        for (int rr = 0; rr < 8; rr++) {
            int it = warp * 8 + rr;
            float p = fmaxf(tbuf[it * LDW + j0] + bb0, 0.f) * w0
                    + fmaxf(tbuf[it * LDW + j1] + bb1, 0.f) * w1;
            #pragma unroll
            for (int o = 16; o; o >>= 1) p += __shfl_xor_sync(~0u, p, o);
            if (lane == 0) sc_s[it] = p + bS2v;
        }
    }
    __syncthreads();

    // ---- Stage C: softmax + context (warps 0..2*TN-1) ----
    if (warp < 2 * TN) {
        int b = warp >> 1, nl = warp & 1;
        float s = (lane < 16) ? sc_s[warp * 16 + lane] * 0.125f : -INFINITY;
        float mx = s;
        #pragma unroll
        for (int o = 16; o; o >>= 1) mx = fmaxf(mx, __shfl_xor_sync(~0u, mx, o));
        float e = (lane < 16) ? __expf(s - mx) : 0.f;
        float se = e;
        #pragma unroll
        for (int o = 16; o; o >>= 1) se += __shfl_xor_sync(~0u, se, o);
        float wt = e / se;
        if (lane < 16) sc_s[warp * 16 + lane] = wt;
        __syncwarp();
        float acc0 = 0.f, acc1 = 0.f;
        #pragma unroll
        for (int kk = 0; kk < 16; kk++) {
            float ww = sc_s[warp * 16 + kk];
            int nb = idx_s[nl * 16 + kk];
            const float* vp  = g_v + ((size_t)b * Nc + nb) * 64;
            const float* rvp = rv_s + (nl * 16 + kk) * LDW;
            acc0 += ww * (vp[lane]      + rvp[lane]);
            acc1 += ww * (vp[lane + 32] + rvp[lane + 32]);
        }
        acc0 += bPv2[lane];
        acc1 += bPv2[lane + 32];
        size_t obase = ((size_t)b * Nc + nbase + nl) * 64;
        g_ctx[obase + lane] = acc0;
        g_ctx[obase + lane + 32] = acc1;
    }
}

// ============================================================
// Kernel: x1 = x + ctx@Wo + bo ; h2 = LN2(x1)
// ============================================================
__global__ void k_wo_ln2(const float* __restrict__ x,
                         const float* __restrict__ Wo, const float* __restrict__ bo,
                         const float* __restrict__ g2, const float* __restrict__ b2) {
    __shared__ float cs[R1][64];
    __shared__ float x1s[R1][Dc];
    const int row0 = blockIdx.x * R1;
    const int tid = threadIdx.x, lane = tid & 31, w = tid >> 5;

    for (int i = tid; i < R1 * 64; i += 256)
        cs[i >> 6][i & 63] = g_ctx[(size_t)row0 * 64 + i];
    __syncthreads();

    const int col = tid;
    float acc[R1];
    #pragma unroll
    for (int r = 0; r < R1; r++) acc[r] = 0.f;
    #pragma unroll 4
    for (int v = 0; v < 64; v++) {
        float wv = Wo[v * Dc + col];
        #pragma unroll
        for (int r = 0; r < R1; r++) acc[r] += cs[r][v] * wv;
    }
    float bov = bo[col];
    #pragma unroll
    for (int r = 0; r < R1; r++) {
        float val = x[(size_t)(row0 + r) * Dc + col] + acc[r] + bov;
        x1s[r][col] = val;
        g_x1[(size_t)(row0 + r) * Dc + col] = val;
    }
    __syncthreads();

    #pragma unroll
    for (int rr = 0; rr < 2; rr++) {
        int r = w * 2 + rr;
        float s = 0.f;
        #pragma unroll
        for (int i = 0; i < Dc / 32; i++) s += x1s[r][lane + 32 * i];
        #pragma unroll
        for (int o = 16; o; o >>= 1) s += __shfl_xor_sync(~0u, s, o);
        float m = s * (1.0f / Dc);
        float v = 0.f;
        #pragma unroll
        for (int i = 0; i < Dc / 32; i++) { float d = x1s[r][lane + 32 * i] - m; v += d * d; }
        #pragma unroll
        for (int o = 16; o; o >>= 1) v += __shfl_xor_sync(~0u, v, o);
        float rstd = rsqrtf(v * (1.0f / Dc) + 1e-5f);
        #pragma unroll
        for (int i = 0; i < Dc / 32; i++) {
            int d = lane + 32 * i;
            g_h2[(size_t)(row0 + r) * Dc + d] = (x1s[r][d] - m) * rstd * g2[d] + b2[d];
        }
    }
}

// ============================================================
extern "C" void kernel_launch(void* const* d_in, const int* in_sizes, int n_in,
                              void* d_out, int out_size) {
    const float* x       = (const float*)d_in[0];
    const int*   knn_idx = (const int*)  d_in[1];
    const float* rel     = (const float*)d_in[2];
    const float* g1 = (const float*)d_in[3];
    const float* b1 = (const float*)d_in[4];
    const float* g2 = (const float*)d_in[5];
    const float* b2 = (const float*)d_in[6];
    const float* Wq = (const float*)d_in[7];
    const float* bq = (const float*)d_in[8];
    const float* Wk = (const float*)d_in[9];
    const float* bk = (const float*)d_in[10];
    const float* Wv = (const float*)d_in[11];
    const float* bv = (const float*)d_in[12];
    const float* Wo = (const float*)d_in[13];
    const float* bo = (const float*)d_in[14];
    const float* Wpa1 = (const float*)d_in[15];
    const float* bpa1 = (const float*)d_in[16];
    const float* Wpa2 = (const float*)d_in[17];
    const float* bpa2 = (const float*)d_in[18];
    const float* Wpv1 = (const float*)d_in[19];
    const float* bpv1 = (const float*)d_in[20];
    const float* Wpv2 = (const float*)d_in[21];
    const float* bpv2 = (const float*)d_in[22];
    const float* Ws1  = (const float*)d_in[23];
    const float* bs1  = (const float*)d_in[24];
    const float* Ws2  = (const float*)d_in[25];
    const float* bs2  = (const float*)d_in[26];
    const float* Wf1  = (const float*)d_in[27];
    const float* bf1  = (const float*)d_in[28];
    const float* Wf2  = (const float*)d_in[29];
    const float* bf2  = (const float*)d_in[30];
    float* out = (float*)d_out;

    float *p_ln, *p_x1, *p_h2, *p_hid;
    cudaGetSymbolAddress((void**)&p_ln,  g_ln);
    cudaGetSymbolAddress((void**)&p_x1,  g_x1);
    cudaGetSymbolAddress((void**)&p_h2,  g_h2);
    cudaGetSymbolAddress((void**)&p_hid, g_hid);

    // 1. LN1
    k_ln<<<Mrows / 8, 256>>>(x, g1, b1, p_ln);

    // 2. fused QKV projection
    k_qkv<<<dim3(Mrows / BM, 3), 256>>>(p_ln, Wq, bq, Wk, bk, Wv, bv);

    // 3. attention (tensor cores)
    const int smemA = 92160;
    cudaFuncSetAttribute(k_attn, cudaFuncAttributeMaxDynamicSharedMemorySize, smemA);
    k_attn<<<Nc / TN, 256, smemA>>>(knn_idx, rel,
                                    Wpa1, bpa1, Wpa2, bpa2,
                                    Wpv1, bpv1, Wpv2, bpv2,
                                    Ws1, bs1, Ws2, bs2);

    // 4. Wo + residual + LN2
    k_wo_ln2<<<Mrows / R1, 256>>>(x, Wo, bo, g2, b2);

    // 5. FFN
    k_ffn1<<<dim3(Mrows / BM, Hc / BN), 256>>>(p_h2, Wf1, bf1, p_hid);
    k_ffn2<<<dim3(Mrows / BM, Dc / BN), 256>>>(p_hid, Wf2, bf2, p_x1, out);
}

// round 6
// speedup vs baseline: 1.9983x; 1.3057x over previous
#include <cuda_runtime.h>
#include <cstdint>
#include <mma.h>
#include <math.h>

using namespace nvcuda;

// Problem constants
#define Bc 2
#define Nc 32768
#define Kc 16
#define Dc 256
#define Ac 64
#define Vc 64
#define Hc 512
#define Mrows (Bc * Nc)   // 65536

#define TN 4              // points per attention block

// -------- scratch (device globals) --------
__device__ float g_ln [(size_t)Mrows * Dc];
__device__ float g_q  [(size_t)Mrows * Ac];
__device__ float g_k  [(size_t)Mrows * Ac];
__device__ float g_v  [(size_t)Mrows * Vc];
__device__ float g_ctx[(size_t)Mrows * Vc];
__device__ float g_x1 [(size_t)Mrows * Dc];
__device__ float g_h2 [(size_t)Mrows * Dc];
__device__ float g_hid[(size_t)Mrows * Hc];

__device__ __forceinline__ float fast_tanh(float x) {
    float y;
    asm("tanh.approx.f32 %0, %1;" : "=f"(y) : "f"(x));
    return y;
}

__device__ __forceinline__ void cp16(float* dst, const float* src) {
    unsigned int s = (unsigned int)__cvta_generic_to_shared(dst);
    asm volatile("cp.async.cg.shared.global [%0], [%1], 16;" :: "r"(s), "l"(src));
}
__device__ __forceinline__ void cp_commit() {
    asm volatile("cp.async.commit_group;" ::: "memory");
}
__device__ __forceinline__ void cp_wait0() {
    asm volatile("cp.async.wait_group 0;" ::: "memory");
}

// ============================================================
// LayerNorm: out = LN(in)*g + b.  one warp per row.
// ============================================================
__global__ void k_ln(const float* __restrict__ in,
                     const float* __restrict__ g, const float* __restrict__ b,
                     float* __restrict__ out) {
    const int row = blockIdx.x * 8 + (threadIdx.x >> 5);
    const int lane = threadIdx.x & 31;
    const float* p = in + (size_t)row * Dc;
    float v[8];
    #pragma unroll
    for (int i = 0; i < 8; i++) v[i] = p[lane + 32 * i];
    float s = 0.f;
    #pragma unroll
    for (int i = 0; i < 8; i++) s += v[i];
    #pragma unroll
    for (int o = 16; o; o >>= 1) s += __shfl_xor_sync(~0u, s, o);
    float m = s * (1.0f / Dc);
    float var = 0.f;
    #pragma unroll
    for (int i = 0; i < 8; i++) { float d = v[i] - m; var += d * d; }
    #pragma unroll
    for (int o = 16; o; o >>= 1) var += __shfl_xor_sync(~0u, var, o);
    float rstd = rsqrtf(var * (1.0f / Dc) + 1e-5f);
    float* q = out + (size_t)row * Dc;
    #pragma unroll
    for (int i = 0; i < 8; i++) {
        int d = lane + 32 * i;
        q[d] = (v[i] - m) * rstd * g[d] + b[d];
    }
}

// ============================================================
// Pipelined tf32 wmma GEMM core.  BM=128, BK=32, BN template.
// 8 warps: wm = warp&3 (32-row slab), wn = warp>>2 (WCOLS-col slab)
// ============================================================
#define BM 128
#define BK 32

template<int BN_, int ACT, bool HAS_RES>
__device__ __forceinline__ void gemm_core2(const float* __restrict__ A, const float* __restrict__ B,
                                           const float* __restrict__ bias, const float* __restrict__ Res,
                                           float* __restrict__ C, int N, int K, int row0, int col0) {
    constexpr int LDA_ = BK + 4;            // 36
    constexpr int LDB_ = BN_ + 4;           // 68 or 132
    constexpr int ASZ  = BM * LDA_;         // 4608
    constexpr int BSZ  = BK * LDB_;         // 2176 or 4224
    constexpr int NFRAG = BN_ / 32;         // 2 or 4
    constexpr int WCOLS = 16 * NFRAG;       // 32 or 64
    constexpr int LDE_  = WCOLS + 4;

    extern __shared__ float smem[];
    float* Abuf[2] = { smem, smem + ASZ + BSZ };
    float* Bbuf[2] = { smem + ASZ, smem + 2 * ASZ + BSZ };

    const int tid = threadIdx.x;
    const int warp = tid >> 5, lane = tid & 31;
    const int wm = warp & 3;
    const int wn = warp >> 2;

    wmma::fragment<wmma::accumulator, 16, 16, 8, float> cf[2][NFRAG];
    #pragma unroll
    for (int i = 0; i < 2; i++)
        #pragma unroll
        for (int j = 0; j < NFRAG; j++) wmma::fill_fragment(cf[i][j], 0.f);

    // preamble: issue first tile
    {
        #pragma unroll
        for (int i = 0; i < 4; i++) {
            int idx = tid + i * 256;
            int r = idx >> 3, c4 = idx & 7;
            cp16(&Abuf[0][r * LDA_ + c4 * 4], A + (size_t)(row0 + r) * K + c4 * 4);
        }
        #pragma unroll
        for (int i = 0; i < BN_ / 32; i++) {
            int idx = tid + i * 256;
            int r = idx / (BN_ / 4), c4 = idx % (BN_ / 4);
            cp16(&Bbuf[0][r * LDB_ + c4 * 4], B + (size_t)r * N + col0 + c4 * 4);
        }
        cp_commit();
    }

    int buf = 0;
    for (int k0 = 0; k0 < K; k0 += BK) {
        cp_wait0();
        __syncthreads();
        if (k0 + BK < K) {
            float* As = Abuf[buf ^ 1];
            float* Bs = Bbuf[buf ^ 1];
            #pragma unroll
            for (int i = 0; i < 4; i++) {
                int idx = tid + i * 256;
                int r = idx >> 3, c4 = idx & 7;
                cp16(&As[r * LDA_ + c4 * 4], A + (size_t)(row0 + r) * K + (k0 + BK) + c4 * 4);
            }
            #pragma unroll
            for (int i = 0; i < BN_ / 32; i++) {
                int idx = tid + i * 256;
                int r = idx / (BN_ / 4), c4 = idx % (BN_ / 4);
                cp16(&Bs[r * LDB_ + c4 * 4], B + (size_t)(k0 + BK + r) * N + col0 + c4 * 4);
            }
            cp_commit();
        }
        const float* As = Abuf[buf];
        const float* Bs = Bbuf[buf];
        #pragma unroll
        for (int kk = 0; kk < BK; kk += 8) {
            wmma::fragment<wmma::matrix_a, 16, 16, 8, wmma::precision::tf32, wmma::row_major> af[2];
            wmma::fragment<wmma::matrix_b, 16, 16, 8, wmma::precision::tf32, wmma::row_major> bf[NFRAG];
            #pragma unroll
            for (int i = 0; i < 2; i++) {
                wmma::load_matrix_sync(af[i], &As[(wm * 32 + i * 16) * LDA_ + kk], LDA_);
                #pragma unroll
                for (int t = 0; t < af[i].num_elements; t++)
                    af[i].x[t] = wmma::__float_to_tf32(af[i].x[t]);
            }
            #pragma unroll
            for (int j = 0; j < NFRAG; j++) {
                wmma::load_matrix_sync(bf[j], &Bs[kk * LDB_ + wn * WCOLS + j * 16], LDB_);
                #pragma unroll
                for (int t = 0; t < bf[j].num_elements; t++)
                    bf[j].x[t] = wmma::__float_to_tf32(bf[j].x[t]);
            }
            #pragma unroll
            for (int i = 0; i < 2; i++)
                #pragma unroll
                for (int j = 0; j < NFRAG; j++)
                    wmma::mma_sync(cf[i][j], af[i], bf[j], cf[i][j]);
        }
        buf ^= 1;
    }

    // epilogue: reuse smem for per-warp staging
    __syncthreads();
    float* Ep = smem + warp * (32 * LDE_);
    #pragma unroll
    for (int i = 0; i < 2; i++)
        #pragma unroll
        for (int j = 0; j < NFRAG; j++)
            wmma::store_matrix_sync(&Ep[i * 16 * LDE_ + j * 16], cf[i][j], LDE_, wmma::mem_row_major);
    __syncwarp();

    const int gr0 = row0 + wm * 32;
    const int gcb = col0 + wn * WCOLS;
    #pragma unroll
    for (int cc = 0; cc < WCOLS / 32; cc++) {
        const int cI = lane + cc * 32;
        const float bv = bias[gcb + cI];
        #pragma unroll 4
        for (int r = 0; r < 32; r++) {
            float z = Ep[r * LDE_ + cI] + bv;
            if (ACT == 1) z = 0.5f * z * (1.f + erff(z * 0.70710678118654752f));
            if (HAS_RES) z += Res[(size_t)(gr0 + r) * N + gcb + cI];
            C[(size_t)(gr0 + r) * N + gcb + cI] = z;
        }
    }
}

// fused QKV: grid.y = {0,1,2}
__global__ void __launch_bounds__(256, 2) k_qkv(const float* __restrict__ A,
                      const float* __restrict__ Wq, const float* __restrict__ bq,
                      const float* __restrict__ Wk, const float* __restrict__ bk,
                      const float* __restrict__ Wv, const float* __restrict__ bv) {
    const float* B; const float* bias; float* C;
    if (blockIdx.y == 0)      { B = Wq; bias = bq; C = g_q; }
    else if (blockIdx.y == 1) { B = Wk; bias = bk; C = g_k; }
    else                      { B = Wv; bias = bv; C = g_v; }
    gemm_core2<64, 0, false>(A, B, bias, nullptr, C, 64, Dc, blockIdx.x * BM, 0);
}

__global__ void __launch_bounds__(256, 2) k_wo(const float* __restrict__ x,
                     const float* __restrict__ Wo, const float* __restrict__ bo) {
    gemm_core2<128, 0, true>(g_ctx, Wo, bo, x, g_x1, Dc, Vc, blockIdx.x * BM, blockIdx.y * 128);
}

__global__ void __launch_bounds__(256, 2) k_ffn1(const float* __restrict__ B,
                       const float* __restrict__ bias) {
    gemm_core2<128, 1, false>(g_h2, B, bias, nullptr, g_hid, Hc, Dc, blockIdx.x * BM, blockIdx.y * 128);
}

__global__ void __launch_bounds__(256, 2) k_ffn2(const float* __restrict__ B,
                       const float* __restrict__ bias, float* __restrict__ C) {
    gemm_core2<128, 0, true>(g_hid, B, bias, g_x1, C, Dc, Hc, blockIdx.x * BM, blockIdx.y * 128);
}

// ============================================================
// Attention kernel (tensor cores), TN=4, chunked score stage
// grid = Nc/TN, 256 threads (8 warps)
// ============================================================
#define LDW 68

__global__ void __launch_bounds__(256) k_attn(
                       const int* __restrict__ knn_idx,
                       const float* __restrict__ rel,
                       const float* __restrict__ Wpa1, const float* __restrict__ bpa1,
                       const float* __restrict__ Wpa2, const float* __restrict__ bpa2,
                       const float* __restrict__ Wpv1, const float* __restrict__ bpv1,
                       const float* __restrict__ Wpv2, const float* __restrict__ bpv2,
                       const float* __restrict__ Ws1,  const float* __restrict__ bs1,
                       const float* __restrict__ Ws2,  const float* __restrict__ bs2) {
    extern __shared__ float sm[];
    float* wPa2 = sm;               // [64][68] = 4352
    float* wPv2 = wPa2 + 4352;      // 4352
    float* wS1s = wPv2 + 4352;      // 4352
    float* wPa1 = wS1s + 4352;      // 192
    float* wPv1 = wPa1 + 192;       // 192
    float* bPa1 = wPv1 + 192;       // 64
    float* bPv1 = bPa1 + 64;        // 64
    float* bPa2 = bPv1 + 64;        // 64
    float* bPv2 = bPa2 + 64;        // 64
    float* bS1s = bPv2 + 64;        // 64
    float* wS2s = bS1s + 64;        // 64
    float* qs   = wS2s + 64;        // 512  (2*TN*64)
    float* rel_s= qs + 512;         // 192  (TN*16*3)
    float* ra_s = rel_s + 192;      // [64][68] = 4352
    float* rv_s = ra_s + 4352;      // 4352
    float* tbuf = rv_s + 4352;      // [64][68] = 4352
    float* sc_s = tbuf + 4352;      // 128
    int*  idx_s = (int*)(sc_s + 128);// 64

    const int tid = threadIdx.x, lane = tid & 31, warp = tid >> 5;
    const int nbase = blockIdx.x * TN;

    // ---- cooperative loads ----
    for (int i = tid; i < 4096; i += 256) {
        int r = i >> 6, c = i & 63;
        wPa2[r * LDW + c] = Wpa2[i];
        wPv2[r * LDW + c] = Wpv2[i];
        wS1s[r * LDW + c] = Ws1[i];
    }
    for (int i = tid; i < 192; i += 256) {
        wPa1[i] = Wpa1[i]; wPv1[i] = Wpv1[i];
        rel_s[i] = rel[(size_t)nbase * Kc * 3 + i];
    }
    if (tid < 64) {
        bPa1[tid] = bpa1[tid]; bPv1[tid] = bpv1[tid];
        bPa2[tid] = bpa2[tid]; bPv2[tid] = bpv2[tid];
        bS1s[tid] = bs1[tid];  wS2s[tid] = Ws2[tid];
        idx_s[tid] = knn_idx[(size_t)nbase * Kc + tid];
    }
    for (int i = tid; i < 2 * TN * 64; i += 256) {
        int b = i >> 8, nl = (i >> 6) & (TN - 1), a = i & 63;
        qs[i] = g_q[((size_t)b * Nc + nbase + nl) * 64 + a];
    }
    const float bS2v = bs2[0];
    __syncthreads();

    // ---- Stage A: ra/rv via wmma (64x64 @ 64x64) ----
    #pragma unroll
    for (int pp = 0; pp < 2; pp++) {
        const float* W1 = pp ? wPv1 : wPa1;
        const float* B1 = pp ? bPv1 : bPa1;
        const float* W2 = pp ? wPv2 : wPa2;
        float* dst = pp ? rv_s : ra_s;

        for (int i = tid; i < 64 * 64; i += 256) {
            int r = i >> 6, j = i & 63;
            float r0 = rel_s[r * 3], r1 = rel_s[r * 3 + 1], r2 = rel_s[r * 3 + 2];
            float h = fmaf(r2, W1[128 + j], fmaf(r1, W1[64 + j], fmaf(r0, W1[j], B1[j])));
            tbuf[r * LDW + j] = fmaxf(h, 0.f);
        }
        __syncthreads();
        {
            const int mt = warp >> 1, nt2 = (warp & 1) * 2;
            wmma::fragment<wmma::accumulator, 16, 16, 8, float> acc[2];
            wmma::fill_fragment(acc[0], 0.f);
            wmma::fill_fragment(acc[1], 0.f);
            #pragma unroll
            for (int kk = 0; kk < 64; kk += 8) {
                wmma::fragment<wmma::matrix_a, 16, 16, 8, wmma::precision::tf32, wmma::row_major> af;
                wmma::fragment<wmma::matrix_b, 16, 16, 8, wmma::precision::tf32, wmma::row_major> bf[2];
                wmma::load_matrix_sync(af, &tbuf[(mt * 16) * LDW + kk], LDW);
                #pragma unroll
                for (int t = 0; t < af.num_elements; t++) af.x[t] = wmma::__float_to_tf32(af.x[t]);
                #pragma unroll
                for (int j = 0; j < 2; j++) {
                    wmma::load_matrix_sync(bf[j], &W2[kk * LDW + (nt2 + j) * 16], LDW);
                    #pragma unroll
                    for (int t = 0; t < bf[j].num_elements; t++) bf[j].x[t] = wmma::__float_to_tf32(bf[j].x[t]);
                    wmma::mma_sync(acc[j], af, bf[j], acc[j]);
                }
            }
            wmma::store_matrix_sync(&dst[(mt * 16) * LDW + nt2 * 16],       acc[0], LDW, wmma::mem_row_major);
            wmma::store_matrix_sync(&dst[(mt * 16) * LDW + (nt2 + 1) * 16], acc[1], LDW, wmma::mem_row_major);
        }
        __syncthreads();
    }

    // ---- Stage B: scores, chunked by batch (chunk c = batch c) ----
    #pragma unroll
    for (int c = 0; c < 2; c++) {
        for (int i = tid; i < 64 * 64; i += 256) {
            int it = i >> 6, a = i & 63;
            int nl = it >> 4, kk = it & 15;
            int nb = idx_s[nl * 16 + kk];
            float kv = __ldg(&g_k[((size_t)c * Nc + nb) * 64 + a]);
            float t = qs[(c * TN + nl) * 64 + a] - kv + ra_s[(nl * 16 + kk) * LDW + a] + bPa2[a];
            tbuf[it * LDW + a] = fast_tanh(t);
        }
        __syncthreads();
        {
            const int mt = warp >> 1, nt2 = (warp & 1) * 2;
            wmma::fragment<wmma::accumulator, 16, 16, 8, float> acc[2];
            wmma::fill_fragment(acc[0], 0.f);
            wmma::fill_fragment(acc[1], 0.f);
            #pragma unroll
            for (int kk = 0; kk < 64; kk += 8) {
                wmma::fragment<wmma::matrix_a, 16, 16, 8, wmma::precision::tf32, wmma::row_major> af;
                wmma::fragment<wmma::matrix_b, 16, 16, 8, wmma::precision::tf32, wmma::row_major> bf[2];
                wmma::load_matrix_sync(af, &tbuf[(mt * 16) * LDW + kk], LDW);
                #pragma unroll
                for (int t = 0; t < af.num_elements; t++) af.x[t] = wmma::__float_to_tf32(af.x[t]);
                #pragma unroll
                for (int j = 0; j < 2; j++) {
                    wmma::load_matrix_sync(bf[j], &wS1s[kk * LDW + (nt2 + j) * 16], LDW);
                    #pragma unroll
                    for (int t = 0; t < bf[j].num_elements; t++) bf[j].x[t] = wmma::__float_to_tf32(bf[j].x[t]);
                    wmma::mma_sync(acc[j], af, bf[j], acc[j]);
                }
            }
            __syncthreads();   // tbuf reads done before overwrite with u
            wmma::store_matrix_sync(&tbuf[(mt * 16) * LDW + nt2 * 16],       acc[0], LDW, wmma::mem_row_major);
            wmma::store_matrix_sync(&tbuf[(mt * 16) * LDW + (nt2 + 1) * 16], acc[1], LDW, wmma::mem_row_major);
        }
        __syncthreads();
        {
            const int j0 = 2 * lane, j1 = 2 * lane + 1;
            float w0 = wS2s[j0], w1 = wS2s[j1];
            float bb0 = bS1s[j0], bb1 = bS1s[j1];
            #pragma unroll
            for (int rr = 0; rr < 8; rr++) {
                int it = warp * 8 + rr;
                float p = fmaxf(tbuf[it * LDW + j0] + bb0, 0.f) * w0
                        + fmaxf(tbuf[it * LDW + j1] + bb1, 0.f) * w1;
                #pragma unroll
                for (int o = 16; o; o >>= 1) p += __shfl_xor_sync(~0u, p, o);
                if (lane == 0) sc_s[c * 64 + it] = p + bS2v;
            }
        }
        __syncthreads();
    }

    // ---- Stage C: softmax + context, warp = b*TN + nl ----
    {
        int b = warp >> 2, nl = warp & 3;
        float s = (lane < 16) ? sc_s[warp * 16 + lane] * 0.125f : -INFINITY;
        float mx = s;
        #pragma unroll
        for (int o = 16; o; o >>= 1) mx = fmaxf(mx, __shfl_xor_sync(~0u, mx, o));
        float e = (lane < 16) ? __expf(s - mx) : 0.f;
        float se = e;
        #pragma unroll
        for (int o = 16; o; o >>= 1) se += __shfl_xor_sync(~0u, se, o);
        float wt = e / se;
        if (lane < 16) sc_s[warp * 16 + lane] = wt;
        __syncwarp();
        float acc0 = 0.f, acc1 = 0.f;
        #pragma unroll
        for (int kk = 0; kk < 16; kk++) {
            float ww = sc_s[warp * 16 + kk];
            int nb = idx_s[nl * 16 + kk];
            const float* vp  = g_v + ((size_t)b * Nc + nb) * 64;
            const float* rvp = rv_s + (nl * 16 + kk) * LDW;
            acc0 += ww * (vp[lane]      + rvp[lane]);
            acc1 += ww * (vp[lane + 32] + rvp[lane + 32]);
        }
        acc0 += bPv2[lane];
        acc1 += bPv2[lane + 32];
        size_t obase = ((size_t)b * Nc + nbase + nl) * 64;
        g_ctx[obase + lane] = acc0;
        g_ctx[obase + lane + 32] = acc1;
    }
}

// ============================================================
extern "C" void kernel_launch(void* const* d_in, const int* in_sizes, int n_in,
                              void* d_out, int out_size) {
    const float* x       = (const float*)d_in[0];
    const int*   knn_idx = (const int*)  d_in[1];
    const float* rel     = (const float*)d_in[2];
    const float* g1 = (const float*)d_in[3];
    const float* b1 = (const float*)d_in[4];
    const float* g2 = (const float*)d_in[5];
    const float* b2 = (const float*)d_in[6];
    const float* Wq = (const float*)d_in[7];
    const float* bq = (const float*)d_in[8];
    const float* Wk = (const float*)d_in[9];
    const float* bk = (const float*)d_in[10];
    const float* Wv = (const float*)d_in[11];
    const float* bv = (const float*)d_in[12];
    const float* Wo = (const float*)d_in[13];
    const float* bo = (const float*)d_in[14];
    const float* Wpa1 = (const float*)d_in[15];
    const float* bpa1 = (const float*)d_in[16];
    const float* Wpa2 = (const float*)d_in[17];
    const float* bpa2 = (const float*)d_in[18];
    const float* Wpv1 = (const float*)d_in[19];
    const float* bpv1 = (const float*)d_in[20];
    const float* Wpv2 = (const float*)d_in[21];
    const float* bpv2 = (const float*)d_in[22];
    const float* Ws1  = (const float*)d_in[23];
    const float* bs1  = (const float*)d_in[24];
    const float* Ws2  = (const float*)d_in[25];
    const float* bs2  = (const float*)d_in[26];
    const float* Wf1  = (const float*)d_in[27];
    const float* bf1  = (const float*)d_in[28];
    const float* Wf2  = (const float*)d_in[29];
    const float* bf2  = (const float*)d_in[30];
    float* out = (float*)d_out;

    float *p_ln, *p_x1, *p_h2;
    cudaGetSymbolAddress((void**)&p_ln,  g_ln);
    cudaGetSymbolAddress((void**)&p_x1,  g_x1);
    cudaGetSymbolAddress((void**)&p_h2,  g_h2);

    const int smemQKV = 2 * (BM * 36 + BK * 68)  * 4;   // 54272
    const int smem128 = 2 * (BM * 36 + BK * 132) * 4;   // 70656
    const int smemA   = 27776 * 4;                       // 111104

    static bool attr_done = false;
    if (!attr_done) {
        cudaFuncSetAttribute(k_qkv,  cudaFuncAttributeMaxDynamicSharedMemorySize, smemQKV);
        cudaFuncSetAttribute(k_wo,   cudaFuncAttributeMaxDynamicSharedMemorySize, smem128);
        cudaFuncSetAttribute(k_ffn1, cudaFuncAttributeMaxDynamicSharedMemorySize, smem128);
        cudaFuncSetAttribute(k_ffn2, cudaFuncAttributeMaxDynamicSharedMemorySize, smem128);
        cudaFuncSetAttribute(k_attn, cudaFuncAttributeMaxDynamicSharedMemorySize, smemA);
        attr_done = true;
    }

    // 1. LN1
    k_ln<<<Mrows / 8, 256>>>(x, g1, b1, p_ln);

    // 2. fused QKV projection
    k_qkv<<<dim3(Mrows / BM, 3), 256, smemQKV>>>(p_ln, Wq, bq, Wk, bk, Wv, bv);

    // 3. attention
    k_attn<<<Nc / TN, 256, smemA>>>(knn_idx, rel,
                                    Wpa1, bpa1, Wpa2, bpa2,
                                    Wpv1, bpv1, Wpv2, bpv2,
                                    Ws1, bs1, Ws2, bs2);

    // 4. x1 = x + ctx@Wo + bo ; h2 = LN2(x1)
    k_wo<<<dim3(Mrows / BM, Dc / 128), 256, smem128>>>(x, Wo, bo);
    k_ln<<<Mrows / 8, 256>>>(p_x1, g2, b2, p_h2);

    // 5. FFN
    k_ffn1<<<dim3(Mrows / BM, Hc / 128), 256, smem128>>>(Wf1, bf1);
    k_ffn2<<<dim3(Mrows / BM, Dc / 128), 256, smem128>>>(Wf2, bf2, out);
}

// round 7
// speedup vs baseline: 3.0093x; 1.5059x over previous
#include <cuda_runtime.h>
#include <cstdint>
#include <cuda_bf16.h>
#include <mma.h>
#include <math.h>

using namespace nvcuda;

// Problem constants
#define Bc 2
#define Nc 32768
#define Kc 16
#define Dc 256
#define Ac 64
#define Vc 64
#define Hc 512
#define Mrows (Bc * Nc)   // 65536

#define TN 4              // points per attention block

typedef __nv_bfloat16 bf16;

// -------- scratch (device globals) --------
__device__ bf16  g_lnb [(size_t)Mrows * Dc];   // LN1 out (bf16 A-operand)
__device__ float g_q   [(size_t)Mrows * Ac];
__device__ float g_k   [(size_t)Mrows * Ac];
__device__ float g_v   [(size_t)Mrows * Vc];
__device__ bf16  g_ctxb[(size_t)Mrows * Vc];   // attention out
__device__ float g_x1  [(size_t)Mrows * Dc];   // residual stream (fp32)
__device__ bf16  g_h2b [(size_t)Mrows * Dc];   // LN2 out
__device__ bf16  g_hidb[(size_t)Mrows * Hc];   // FFN hidden

// bf16 weight copies
__device__ bf16 g_Wqb [Dc * Ac];
__device__ bf16 g_Wkb [Dc * Ac];
__device__ bf16 g_Wvb [Dc * Vc];
__device__ bf16 g_Wob [Vc * Dc];
__device__ bf16 g_Wf1b[Dc * Hc];
__device__ bf16 g_Wf2b[Hc * Dc];

__device__ __forceinline__ float fast_tanh(float x) {
    float y;
    asm("tanh.approx.f32 %0, %1;" : "=f"(y) : "f"(x));
    return y;
}

__device__ __forceinline__ void cp16(void* dst, const void* src) {
    unsigned int s = (unsigned int)__cvta_generic_to_shared(dst);
    asm volatile("cp.async.cg.shared.global [%0], [%1], 16;" :: "r"(s), "l"(src));
}
__device__ __forceinline__ void cp_commit() {
    asm volatile("cp.async.commit_group;" ::: "memory");
}
__device__ __forceinline__ void cp_wait0() {
    asm volatile("cp.async.wait_group 0;" ::: "memory");
}

// ============================================================
// Weight fp32 -> bf16 conversion (one pass, tiny)
// ============================================================
__global__ void k_cvtw(const float* __restrict__ Wq, const float* __restrict__ Wk,
                       const float* __restrict__ Wv, const float* __restrict__ Wo,
                       const float* __restrict__ Wf1, const float* __restrict__ Wf2) {
    int i = blockIdx.x * blockDim.x + threadIdx.x;
    const int S1 = Dc * Ac;          // 16384
    const int S2 = S1 * 2;
    const int S3 = S1 * 3;
    const int S4 = S3 + Vc * Dc;     // +16384
    const int S5 = S4 + Dc * Hc;     // +131072
    const int S6 = S5 + Hc * Dc;     // +131072
    if (i >= S6) return;
    if (i < S1)       g_Wqb [i]      = __float2bfloat16(Wq [i]);
    else if (i < S2)  g_Wkb [i - S1] = __float2bfloat16(Wk [i - S1]);
    else if (i < S3)  g_Wvb [i - S2] = __float2bfloat16(Wv [i - S2]);
    else if (i < S4)  g_Wob [i - S3] = __float2bfloat16(Wo [i - S3]);
    else if (i < S5)  g_Wf1b[i - S4] = __float2bfloat16(Wf1[i - S4]);
    else              g_Wf2b[i - S5] = __float2bfloat16(Wf2[i - S5]);
}

// ============================================================
// LayerNorm: out(bf16) = LN(in)*g + b.  one warp per row.
// ============================================================
__global__ void k_ln(const float* __restrict__ in,
                     const float* __restrict__ g, const float* __restrict__ b,
                     bf16* __restrict__ out) {
    const int row = blockIdx.x * 8 + (threadIdx.x >> 5);
    const int lane = threadIdx.x & 31;
    const float* p = in + (size_t)row * Dc;
    float v[8];
    #pragma unroll
    for (int i = 0; i < 8; i++) v[i] = p[lane + 32 * i];
    float s = 0.f;
    #pragma unroll
    for (int i = 0; i < 8; i++) s += v[i];
    #pragma unroll
    for (int o = 16; o; o >>= 1) s += __shfl_xor_sync(~0u, s, o);
    float m = s * (1.0f / Dc);
    float var = 0.f;
    #pragma unroll
    for (int i = 0; i < 8; i++) { float d = v[i] - m; var += d * d; }
    #pragma unroll
    for (int o = 16; o; o >>= 1) var += __shfl_xor_sync(~0u, var, o);
    float rstd = rsqrtf(var * (1.0f / Dc) + 1e-5f);
    bf16* q = out + (size_t)row * Dc;
    #pragma unroll
    for (int i = 0; i < 8; i++) {
        int d = lane + 32 * i;
        q[d] = __float2bfloat16((v[i] - m) * rstd * g[d] + b[d]);
    }
}

// ============================================================
// Pipelined bf16 wmma GEMM core.  BM=128, BK=32, BN template.
// 8 warps: wm = warp&3 (32-row slab), wn = warp>>2 (WCOLS-col slab)
// ============================================================
#define BM 128
#define BK 32

template<int BN_, int ACT, bool HAS_RES, bool OUT_BF16>
__device__ __forceinline__ void gemm_core_bf16(
        const bf16* __restrict__ A, const bf16* __restrict__ B,
        const float* __restrict__ bias, const float* __restrict__ Res,
        void* __restrict__ Cv, int N, int K, int row0, int col0) {
    constexpr int LDA_ = BK + 8;            // 40 bf16
    constexpr int LDB_ = BN_ + 8;           // 72 / 136
    constexpr int ASZ  = BM * LDA_;         // 5120
    constexpr int BSZ  = BK * LDB_;         // 2304 / 4352
    constexpr int NFRAG = BN_ / 32;         // 2 / 4
    constexpr int WCOLS = 16 * NFRAG;       // 32 / 64
    constexpr int LDE_  = WCOLS + 4;
    constexpr int AT = (BM * BK / 8) / 256; // 2
    constexpr int BT = (BK * BN_ / 8 + 255) / 256;

    extern __shared__ char smraw[];
    bf16* sb = (bf16*)smraw;
    bf16* Abuf[2] = { sb, sb + ASZ + BSZ };
    bf16* Bbuf[2] = { sb + ASZ, sb + 2 * ASZ + BSZ };

    const int tid = threadIdx.x;
    const int warp = tid >> 5, lane = tid & 31;
    const int wm = warp & 3;
    const int wn = warp >> 2;

    wmma::fragment<wmma::accumulator, 16, 16, 16, float> cf[2][NFRAG];
    #pragma unroll
    for (int i = 0; i < 2; i++)
        #pragma unroll
        for (int j = 0; j < NFRAG; j++) wmma::fill_fragment(cf[i][j], 0.f);

    // preamble: first tile
    {
        #pragma unroll
        for (int i = 0; i < AT; i++) {
            int idx = tid + i * 256;
            int r = idx >> 2, c8 = (idx & 3) * 8;
            cp16(&Abuf[0][r * LDA_ + c8], A + (size_t)(row0 + r) * K + c8);
        }
        #pragma unroll
        for (int i = 0; i < BT; i++) {
            int idx = tid + i * 256;
            if (BT * 256 == BK * BN_ / 8 || idx < BK * BN_ / 8) {
                int r = idx / (BN_ / 8), c8 = (idx % (BN_ / 8)) * 8;
                cp16(&Bbuf[0][r * LDB_ + c8], B + (size_t)r * N + col0 + c8);
            }
        }
        cp_commit();
    }

    int buf = 0;
    for (int k0 = 0; k0 < K; k0 += BK) {
        cp_wait0();
        __syncthreads();
        if (k0 + BK < K) {
            bf16* As = Abuf[buf ^ 1];
            bf16* Bs = Bbuf[buf ^ 1];
            #pragma unroll
            for (int i = 0; i < AT; i++) {
                int idx = tid + i * 256;
                int r = idx >> 2, c8 = (idx & 3) * 8;
                cp16(&As[r * LDA_ + c8], A + (size_t)(row0 + r) * K + (k0 + BK) + c8);
            }
            #pragma unroll
            for (int i = 0; i < BT; i++) {
                int idx = tid + i * 256;
                if (BT * 256 == BK * BN_ / 8 || idx < BK * BN_ / 8) {
                    int r = idx / (BN_ / 8), c8 = (idx % (BN_ / 8)) * 8;
                    cp16(&Bs[r * LDB_ + c8], B + (size_t)(k0 + BK + r) * N + col0 + c8);
                }
            }
            cp_commit();
        }
        const bf16* As = Abuf[buf];
        const bf16* Bs = Bbuf[buf];
        #pragma unroll
        for (int kk = 0; kk < BK; kk += 16) {
            wmma::fragment<wmma::matrix_a, 16, 16, 16, bf16, wmma::row_major> af[2];
            wmma::fragment<wmma::matrix_b, 16, 16, 16, bf16, wmma::row_major> bf[NFRAG];
            #pragma unroll
            for (int i = 0; i < 2; i++)
                wmma::load_matrix_sync(af[i], &As[(wm * 32 + i * 16) * LDA_ + kk], LDA_);
            #pragma unroll
            for (int j = 0; j < NFRAG; j++)
                wmma::load_matrix_sync(bf[j], &Bs[kk * LDB_ + wn * WCOLS + j * 16], LDB_);
            #pragma unroll
            for (int i = 0; i < 2; i++)
                #pragma unroll
                for (int j = 0; j < NFRAG; j++)
                    wmma::mma_sync(cf[i][j], af[i], bf[j], cf[i][j]);
        }
        buf ^= 1;
    }

    // epilogue: 16-row slabs staged per warp in (reused) smem
    __syncthreads();
    float* fs = (float*)smraw;
    float* Ep = fs + warp * (16 * LDE_);

    const int gr00 = row0 + wm * 32;
    const int gcb  = col0 + wn * WCOLS;
    float bvv[WCOLS / 32];
    #pragma unroll
    for (int cc = 0; cc < WCOLS / 32; cc++) bvv[cc] = bias[gcb + cc * 32 + lane];

    #pragma unroll
    for (int i = 0; i < 2; i++) {
        #pragma unroll
        for (int j = 0; j < NFRAG; j++)
            wmma::store_matrix_sync(&Ep[j * 16], cf[i][j], LDE_, wmma::mem_row_major);
        __syncwarp();
        const int gr0 = gr00 + i * 16;
        #pragma unroll
        for (int cc = 0; cc < WCOLS / 32; cc++) {
            const int cI = lane + cc * 32;
            #pragma unroll 4
            for (int r = 0; r < 16; r++) {
                float z = Ep[r * LDE_ + cI] + bvv[cc];
                if (ACT == 1) z = 0.5f * z * (1.f + erff(z * 0.70710678118654752f));
                if (HAS_RES) z += Res[(size_t)(gr0 + r) * N + gcb + cI];
                size_t off = (size_t)(gr0 + r) * N + gcb + cI;
                if (OUT_BF16) ((bf16*)Cv)[off] = __float2bfloat16(z);
                else          ((float*)Cv)[off] = z;
            }
        }
        __syncwarp();
    }
}

// fused QKV: grid.y = {0,1,2}
__global__ void __launch_bounds__(256, 2) k_qkv() {
    const bf16* B; float* C; int sel = blockIdx.y;
    extern __shared__ char smraw[];
    const float* bias;
    __shared__ const float* bias_s;  // biases passed via launch params below
    // (bias pointers provided through constant globals set by host? simpler: params)
    // -- replaced by parameterized version below --
    (void)B; (void)C; (void)sel; (void)smraw; (void)bias; (void)bias_s;
}

// parameterized kernels
__global__ void __launch_bounds__(256, 2) k_qkv2(const float* __restrict__ bq,
                                                 const float* __restrict__ bk,
                                                 const float* __restrict__ bv) {
    const bf16* B; const float* bias; float* C;
    if (blockIdx.y == 0)      { B = g_Wqb; bias = bq; C = g_q; }
    else if (blockIdx.y == 1) { B = g_Wkb; bias = bk; C = g_k; }
    else                      { B = g_Wvb; bias = bv; C = g_v; }
    gemm_core_bf16<64, 0, false, false>(g_lnb, B, bias, nullptr, C, 64, Dc, blockIdx.x * BM, 0);
}

__global__ void __launch_bounds__(256, 2) k_wo(const float* __restrict__ x,
                                               const float* __restrict__ bo) {
    gemm_core_bf16<128, 0, true, false>(g_ctxb, g_Wob, bo, x, g_x1, Dc, Vc,
                                        blockIdx.x * BM, blockIdx.y * 128);
}

__global__ void __launch_bounds__(256, 2) k_ffn1(const float* __restrict__ bf1) {
    gemm_core_bf16<128, 1, false, true>(g_h2b, g_Wf1b, bf1, nullptr, g_hidb, Hc, Dc,
                                        blockIdx.x * BM, blockIdx.y * 128);
}

__global__ void __launch_bounds__(256, 2) k_ffn2(const float* __restrict__ bf2,
                                                 float* __restrict__ C) {
    gemm_core_bf16<128, 0, true, false>(g_hidb, g_Wf2b, bf2, g_x1, C, Dc, Hc,
                                        blockIdx.x * BM, blockIdx.y * 128);
}

// ============================================================
// Attention kernel (bf16 tensor cores), TN=4
// grid = Nc/TN, 256 threads (8 warps)
// ============================================================
#define LDF 68   // fp32 matrices stride
#define LDB2 72  // bf16 matrices stride

__global__ void __launch_bounds__(256) k_attn(
                       const int* __restrict__ knn_idx,
                       const float* __restrict__ rel,
                       const float* __restrict__ Wpa1, const float* __restrict__ bpa1,
                       const float* __restrict__ Wpa2, const float* __restrict__ bpa2,
                       const float* __restrict__ Wpv1, const float* __restrict__ bpv1,
                       const float* __restrict__ Wpv2, const float* __restrict__ bpv2,
                       const float* __restrict__ Ws1,  const float* __restrict__ bs1,
                       const float* __restrict__ Ws2,  const float* __restrict__ bs2) {
    extern __shared__ float sm[];
    float* ra_s  = sm;               // [64][68] = 4352
    float* rv_s  = ra_s + 4352;      // 4352
    float* ubuf  = rv_s + 4352;      // 4352
    float* qs    = ubuf + 4352;      // 512
    float* rel_s = qs + 512;         // 192
    float* bPa1  = rel_s + 192;      // 64
    float* bPv1  = bPa1 + 64;
    float* bPa2  = bPv1 + 64;
    float* bPv2  = bPa2 + 64;
    float* bS1s  = bPv2 + 64;
    float* wS2s  = bS1s + 64;
    float* wPa1  = wS2s + 64;        // 192
    float* wPv1  = wPa1 + 192;       // 192
    float* sc_s  = wPv1 + 192;       // 128
    int*   idx_s = (int*)(sc_s + 128); // 64
    bf16*  wPa2b = (bf16*)(sc_s + 128 + 64);   // [64][72]
    bf16*  wPv2b = wPa2b + 64 * LDB2;
    bf16*  wS1sb = wPv2b + 64 * LDB2;
    bf16*  tbufb = wS1sb + 64 * LDB2;          // [64][72]

    const int tid = threadIdx.x, lane = tid & 31, warp = tid >> 5;
    const int nbase = blockIdx.x * TN;

    // ---- cooperative loads ----
    for (int i = tid; i < 4096; i += 256) {
        int r = i >> 6, c = i & 63;
        wPa2b[r * LDB2 + c] = __float2bfloat16(Wpa2[i]);
        wPv2b[r * LDB2 + c] = __float2bfloat16(Wpv2[i]);
        wS1sb[r * LDB2 + c] = __float2bfloat16(Ws1[i]);
    }
    for (int i = tid; i < 192; i += 256) {
        wPa1[i] = Wpa1[i]; wPv1[i] = Wpv1[i];
        rel_s[i] = rel[(size_t)nbase * Kc * 3 + i];
    }
    if (tid < 64) {
        bPa1[tid] = bpa1[tid]; bPv1[tid] = bpv1[tid];
        bPa2[tid] = bpa2[tid]; bPv2[tid] = bpv2[tid];
        bS1s[tid] = bs1[tid];  wS2s[tid] = Ws2[tid];
        idx_s[tid] = knn_idx[(size_t)nbase * Kc + tid];
    }
    for (int i = tid; i < 2 * TN * 64; i += 256) {
        int b = i >> 8, nl = (i >> 6) & (TN - 1), a = i & 63;
        qs[i] = g_q[((size_t)b * Nc + nbase + nl) * 64 + a];
    }
    const float bS2v = bs2[0];
    __syncthreads();

    // ---- Stage A: ra/rv via bf16 wmma (64x64 @ 64x64) ----
    #pragma unroll
    for (int pp = 0; pp < 2; pp++) {
        const float* W1 = pp ? wPv1 : wPa1;
        const float* B1 = pp ? bPv1 : bPa1;
        const bf16* W2  = pp ? wPv2b : wPa2b;
        float* dst = pp ? rv_s : ra_s;

        for (int i = tid; i < 64 * 64; i += 256) {
            int r = i >> 6, j = i & 63;
            float r0 = rel_s[r * 3], r1 = rel_s[r * 3 + 1], r2 = rel_s[r * 3 + 2];
            float h = fmaf(r2, W1[128 + j], fmaf(r1, W1[64 + j], fmaf(r0, W1[j], B1[j])));
            tbufb[r * LDB2 + j] = __float2bfloat16(fmaxf(h, 0.f));
        }
        __syncthreads();
        {
            const int mt = warp >> 1, nt2 = (warp & 1) * 2;
            wmma::fragment<wmma::accumulator, 16, 16, 16, float> acc[2];
            wmma::fill_fragment(acc[0], 0.f);
            wmma::fill_fragment(acc[1], 0.f);
            #pragma unroll
            for (int kk = 0; kk < 64; kk += 16) {
                wmma::fragment<wmma::matrix_a, 16, 16, 16, bf16, wmma::row_major> af;
                wmma::fragment<wmma::matrix_b, 16, 16, 16, bf16, wmma::row_major> bfr[2];
                wmma::load_matrix_sync(af, &tbufb[(mt * 16) * LDB2 + kk], LDB2);
                #pragma unroll
                for (int j = 0; j < 2; j++) {
                    wmma::load_matrix_sync(bfr[j], &W2[kk * LDB2 + (nt2 + j) * 16], LDB2);
                    wmma::mma_sync(acc[j], af, bfr[j], acc[j]);
                }
            }
            wmma::store_matrix_sync(&dst[(mt * 16) * LDF + nt2 * 16],       acc[0], LDF, wmma::mem_row_major);
            wmma::store_matrix_sync(&dst[(mt * 16) * LDF + (nt2 + 1) * 16], acc[1], LDF, wmma::mem_row_major);
        }
        __syncthreads();
    }

    // ---- Stage B: scores, chunk c = batch c ----
    #pragma unroll
    for (int c = 0; c < 2; c++) {
        for (int i = tid; i < 64 * 64; i += 256) {
            int it = i >> 6, a = i & 63;
            int nl = it >> 4, kk = it & 15;
            int nb = idx_s[nl * 16 + kk];
            float kv = __ldg(&g_k[((size_t)c * Nc + nb) * 64 + a]);
            float t = qs[(c * TN + nl) * 64 + a] - kv + ra_s[(nl * 16 + kk) * LDF + a] + bPa2[a];
            tbufb[it * LDB2 + a] = __float2bfloat16(fast_tanh(t));
        }
        __syncthreads();
        {
            const int mt = warp >> 1, nt2 = (warp & 1) * 2;
            wmma::fragment<wmma::accumulator, 16, 16, 16, float> acc[2];
            wmma::fill_fragment(acc[0], 0.f);
            wmma::fill_fragment(acc[1], 0.f);
            #pragma unroll
            for (int kk = 0; kk < 64; kk += 16) {
                wmma::fragment<wmma::matrix_a, 16, 16, 16, bf16, wmma::row_major> af;
                wmma::fragment<wmma::matrix_b, 16, 16, 16, bf16, wmma::row_major> bfr[2];
                wmma::load_matrix_sync(af, &tbufb[(mt * 16) * LDB2 + kk], LDB2);
                #pragma unroll
                for (int j = 0; j < 2; j++) {
                    wmma::load_matrix_sync(bfr[j], &wS1sb[kk * LDB2 + (nt2 + j) * 16], LDB2);
                    wmma::mma_sync(acc[j], af, bfr[j], acc[j]);
                }
            }
            wmma::store_matrix_sync(&ubuf[(mt * 16) * LDF + nt2 * 16],       acc[0], LDF, wmma::mem_row_major);
            wmma::store_matrix_sync(&ubuf[(mt * 16) * LDF + (nt2 + 1) * 16], acc[1], LDF, wmma::mem_row_major);
        }
        __syncthreads();
        {
            const int j0 = 2 * lane, j1 = 2 * lane + 1;
            float w0 = wS2s[j0], w1 = wS2s[j1];
            float bb0 = bS1s[j0], bb1 = bS1s[j1];
            #pragma unroll
            for (int rr = 0; rr < 8; rr++) {
                int it = warp * 8 + rr;
                float p = fmaxf(ubuf[it * LDF + j0] + bb0, 0.f) * w0
                        + fmaxf(ubuf[it * LDF + j1] + bb1, 0.f) * w1;
                #pragma unroll
                for (int o = 16; o; o >>= 1) p += __shfl_xor_sync(~0u, p, o);
                if (lane == 0) sc_s[c * 64 + it] = p + bS2v;
            }
        }
        __syncthreads();
    }

    // ---- Stage C: softmax + context, warp = b*TN + nl ----
    {
        int b = warp >> 2, nl = warp & 3;
        float s = (lane < 16) ? sc_s[warp * 16 + lane] * 0.125f : -INFINITY;
        float mx = s;
        #pragma unroll
        for (int o = 16; o; o >>= 1) mx = fmaxf(mx, __shfl_xor_sync(~0u, mx, o));
        float e = (lane < 16) ? __expf(s - mx) : 0.f;
        float se = e;
        #pragma unroll
        for (int o = 16; o; o >>= 1) se += __shfl_xor_sync(~0u, se, o);
        float wt = e / se;
        if (lane < 16) sc_s[warp * 16 + lane] = wt;
        __syncwarp();
        float acc0 = 0.f, acc1 = 0.f;
        #pragma unroll
        for (int kk = 0; kk < 16; kk++) {
            float ww = sc_s[warp * 16 + kk];
            int nb = idx_s[nl * 16 + kk];
            const float* vp  = g_v + ((size_t)b * Nc + nb) * 64;
            const float* rvp = rv_s + (nl * 16 + kk) * LDF;
            acc0 += ww * (vp[lane]      + rvp[lane]);
            acc1 += ww * (vp[lane + 32] + rvp[lane + 32]);
        }
        acc0 += bPv2[lane];
        acc1 += bPv2[lane + 32];
        size_t obase = ((size_t)b * Nc + nbase + nl) * 64;
        g_ctxb[obase + lane]      = __float2bfloat16(acc0);
        g_ctxb[obase + lane + 32] = __float2bfloat16(acc1);
    }
}

// ============================================================
extern "C" void kernel_launch(void* const* d_in, const int* in_sizes, int n_in,
                              void* d_out, int out_size) {
    const float* x       = (const float*)d_in[0];
    const int*   knn_idx = (const int*)  d_in[1];
    const float* rel     = (const float*)d_in[2];
    const float* g1 = (const float*)d_in[3];
    const float* b1 = (const float*)d_in[4];
    const float* g2 = (const float*)d_in[5];
    const float* b2 = (const float*)d_in[6];
    const float* Wq = (const float*)d_in[7];
    const float* bq = (const float*)d_in[8];
    const float* Wk = (const float*)d_in[9];
    const float* bk = (const float*)d_in[10];
    const float* Wv = (const float*)d_in[11];
    const float* bv = (const float*)d_in[12];
    const float* Wo = (const float*)d_in[13];
    const float* bo = (const float*)d_in[14];
    const float* Wpa1 = (const float*)d_in[15];
    const float* bpa1 = (const float*)d_in[16];
    const float* Wpa2 = (const float*)d_in[17];
    const float* bpa2 = (const float*)d_in[18];
    const float* Wpv1 = (const float*)d_in[19];
    const float* bpv1 = (const float*)d_in[20];
    const float* Wpv2 = (const float*)d_in[21];
    const float* bpv2 = (const float*)d_in[22];
    const float* Ws1  = (const float*)d_in[23];
    const float* bs1  = (const float*)d_in[24];
    const float* Ws2  = (const float*)d_in[25];
    const float* bs2  = (const float*)d_in[26];
    const float* Wf1  = (const float*)d_in[27];
    const float* bf1  = (const float*)d_in[28];
    const float* Wf2  = (const float*)d_in[29];
    const float* bf2  = (const float*)d_in[30];
    float* out = (float*)d_out;

    float *p_ln, *p_x1;
    bf16 *p_lnb, *p_h2b;
    cudaGetSymbolAddress((void**)&p_lnb, g_lnb);
    cudaGetSymbolAddress((void**)&p_x1,  g_x1);
    cudaGetSymbolAddress((void**)&p_h2b, g_h2b);
    (void)p_ln;

    // smem sizes (bytes)
    const int smemQKV = 2 * (BM * 40 + BK * 72)  * 2;   // 29696
    const int smem128 = 2 * (BM * 40 + BK * 136) * 2;   // 37888
    const int smemA   = 14720 * 4 + 4 * 64 * 72 * 2;    // 95744

    static bool attr_done = false;
    if (!attr_done) {
        cudaFuncSetAttribute(k_qkv2, cudaFuncAttributeMaxDynamicSharedMemorySize, smemQKV);
        cudaFuncSetAttribute(k_wo,   cudaFuncAttributeMaxDynamicSharedMemorySize, smem128);
        cudaFuncSetAttribute(k_ffn1, cudaFuncAttributeMaxDynamicSharedMemorySize, smem128);
        cudaFuncSetAttribute(k_ffn2, cudaFuncAttributeMaxDynamicSharedMemorySize, smem128);
        cudaFuncSetAttribute(k_attn, cudaFuncAttributeMaxDynamicSharedMemorySize, smemA);
        attr_done = true;
    }

    // 0. weights -> bf16
    k_cvtw<<<(327680 + 255) / 256, 256>>>(Wq, Wk, Wv, Wo, Wf1, Wf2);

    // 1. LN1 (bf16 out)
    k_ln<<<Mrows / 8, 256>>>(x, g1, b1, p_lnb);

    // 2. fused QKV
    k_qkv2<<<dim3(Mrows / BM, 3), 256, smemQKV>>>(bq, bk, bv);

    // 3. attention
    k_attn<<<Nc / TN, 256, smemA>>>(knn_idx, rel,
                                    Wpa1, bpa1, Wpa2, bpa2,
                                    Wpv1, bpv1, Wpv2, bpv2,
                                    Ws1, bs1, Ws2, bs2);

    // 4. x1 = x + ctx@Wo + bo ; h2 = LN2(x1) (bf16 out)
    k_wo<<<dim3(Mrows / BM, Dc / 128), 256, smem128>>>(x, bo);
    k_ln<<<Mrows / 8, 256>>>(p_x1, g2, b2, p_h2b);

    // 5. FFN
    k_ffn1<<<dim3(Mrows / BM, Hc / 128), 256, smem128>>>(bf1);
    k_ffn2<<<dim3(Mrows / BM, Dc / 128), 256, smem128>>>(bf2, out);
}